// round 1
// baseline (speedup 1.0000x reference)
#include <cuda_runtime.h>

#define NN 100000
#define EE 1600000
#define DD 128
#define LL 3
#define GG 512

// ---------------- scratch (device globals; no allocation allowed) ----------------
__device__ float g_h[NN * DD];      // current h
__device__ float g_bufA[NN * DD];   // agg/combine output
__device__ float g_bufB[NN * DD];   // after gemm1
__device__ int   g_deg[NN];
__device__ int   g_rowptr[NN + 1];
__device__ int   g_cursor[NN];
__device__ int   g_colidx[EE];
__device__ int   g_bsums[512];
__device__ int   g_gcnt[GG];
__device__ int   g_goff[GG + 1];
__device__ float g_pool[GG * DD];

// ---------------- CSR build ----------------
__global__ void k_zero_deg() {
    int i = blockIdx.x * blockDim.x + threadIdx.x;
    if (i < NN) g_deg[i] = 0;
}

__global__ void k_count(const int* __restrict__ dst) {
    int e = blockIdx.x * blockDim.x + threadIdx.x;
    if (e < EE) atomicAdd(&g_deg[dst[e]], 1);
}

#define SCAN_B 512
// exclusive scan within 512-blocks, write block sums
__global__ void k_scan1() {
    __shared__ int tmp[SCAN_B];
    int t = threadIdx.x;
    int g = blockIdx.x * SCAN_B + t;
    int v = (g < NN) ? g_deg[g] : 0;
    tmp[t] = v;
    __syncthreads();
    for (int off = 1; off < SCAN_B; off <<= 1) {
        int add = (t >= off) ? tmp[t - off] : 0;
        __syncthreads();
        tmp[t] += add;
        __syncthreads();
    }
    if (g < NN) g_rowptr[g] = tmp[t] - v;                 // exclusive within block
    if (t == SCAN_B - 1) g_bsums[blockIdx.x] = tmp[t];    // block total
}

// exclusive scan of block sums (single block, nb <= 256)
__global__ void k_scan2(int nb) {
    __shared__ int tmp[256];
    int t = threadIdx.x;
    int v = (t < nb) ? g_bsums[t] : 0;
    tmp[t] = v;
    __syncthreads();
    for (int off = 1; off < 256; off <<= 1) {
        int add = (t >= off) ? tmp[t - off] : 0;
        __syncthreads();
        tmp[t] += add;
        __syncthreads();
    }
    if (t < nb) g_bsums[t] = tmp[t] - v;
}

__global__ void k_scan3() {
    int t = threadIdx.x;
    int g = blockIdx.x * SCAN_B + t;
    if (g < NN) {
        int val = g_rowptr[g] + g_bsums[blockIdx.x];
        g_rowptr[g] = val;
        g_cursor[g] = val;
        if (g == 0) g_rowptr[NN] = EE;
    }
}

__global__ void k_fill(const int* __restrict__ src, const int* __restrict__ dst) {
    int e = blockIdx.x * blockDim.x + threadIdx.x;
    if (e < EE) {
        int d = dst[e];
        int pos = atomicAdd(&g_cursor[d], 1);
        g_colidx[pos] = src[e];
    }
}

// ---------------- graph (pool) offsets ----------------
__global__ void k_zero_gcnt() {
    int t = threadIdx.x;
    if (t < GG) g_gcnt[t] = 0;
}

__global__ void k_count_batch(const int* __restrict__ batch) {
    int i = blockIdx.x * blockDim.x + threadIdx.x;
    if (i < NN) atomicAdd(&g_gcnt[batch[i]], 1);
}

__global__ void k_scan_g() {
    __shared__ int tmp[GG];
    int t = threadIdx.x;
    int v = g_gcnt[t];
    tmp[t] = v;
    __syncthreads();
    for (int off = 1; off < GG; off <<= 1) {
        int add = (t >= off) ? tmp[t - off] : 0;
        __syncthreads();
        tmp[t] += add;
        __syncthreads();
    }
    g_goff[t] = tmp[t] - v;
    if (t == GG - 1) g_goff[GG] = tmp[t];
}

// ---------------- GIN aggregate + combine: out = (1+eps)*h + sum_nbr(h) ----------------
__global__ void k_agg(const float* __restrict__ h, const float* __restrict__ eps,
                      int layer, float* __restrict__ out) {
    int w = (blockIdx.x * blockDim.x + threadIdx.x) >> 5;
    if (w >= NN) return;
    int lane = threadIdx.x & 31;
    float epsv = 1.0f + __ldg(&eps[layer]);
    const float4* hp = (const float4*)h;
    float4 self = hp[(size_t)w * 32 + lane];
    float ax = self.x * epsv, ay = self.y * epsv, az = self.z * epsv, aw = self.w * epsv;
    int s = g_rowptr[w], e = g_rowptr[w + 1];
    int j = s;
    for (; j + 3 < e; j += 4) {
        int s0 = g_colidx[j], s1 = g_colidx[j + 1], s2 = g_colidx[j + 2], s3 = g_colidx[j + 3];
        float4 v0 = hp[(size_t)s0 * 32 + lane];
        float4 v1 = hp[(size_t)s1 * 32 + lane];
        float4 v2 = hp[(size_t)s2 * 32 + lane];
        float4 v3 = hp[(size_t)s3 * 32 + lane];
        ax += v0.x + v1.x + v2.x + v3.x;
        ay += v0.y + v1.y + v2.y + v3.y;
        az += v0.z + v1.z + v2.z + v3.z;
        aw += v0.w + v1.w + v2.w + v3.w;
    }
    for (; j < e; j++) {
        int s0 = g_colidx[j];
        float4 v = hp[(size_t)s0 * 32 + lane];
        ax += v.x; ay += v.y; az += v.z; aw += v.w;
    }
    float4 r; r.x = ax; r.y = ay; r.z = az; r.w = aw;
    ((float4*)out)[(size_t)w * 32 + lane] = r;
}

// ---------------- fused GEMM: out = epi(A @ W + bias), A:[M,128] W:[128,128] ----------------
// EPI 0: relu(. + bias)
// EPI 1: bn(relu(. + bias))  with running stats
#define GEMM_SMEM ((128 * 64 + 128 * 128) * 4)

template <int EPI>
__global__ void __launch_bounds__(256, 2)
k_gemm(const float* __restrict__ A, const float* __restrict__ W,
       const float* __restrict__ bias,
       const float* __restrict__ gamma, const float* __restrict__ beta,
       const float* __restrict__ rmean, const float* __restrict__ rvar,
       float* __restrict__ out, int M) {
    extern __shared__ float sm[];
    float* sA = sm;                 // [128][64]  A tile, transposed (k-major)
    float* sB = sm + 128 * 64;      // [128][128] W (k-major, as stored)

    int tid = threadIdx.x;
    int base = blockIdx.x * 64;

    // stage W
    {
        const float4* W4 = (const float4*)W;
        float4* sB4 = (float4*)sB;
#pragma unroll
        for (int i = 0; i < 16; i++) sB4[tid + i * 256] = W4[tid + i * 256];
    }
    // stage A (transposed into sA[k][row])
    {
        int r0 = tid >> 5;   // 0..7
        int c4 = tid & 31;   // 0..31 -> cols c4*4..+3
#pragma unroll
        for (int rr = 0; rr < 8; rr++) {
            int row = rr * 8 + r0;
            int grow = base + row;
            float4 v;
            if (grow < M) v = *(const float4*)&A[(size_t)grow * DD + c4 * 4];
            else { v.x = 0.f; v.y = 0.f; v.z = 0.f; v.w = 0.f; }
            sA[(c4 * 4 + 0) * 64 + row] = v.x;
            sA[(c4 * 4 + 1) * 64 + row] = v.y;
            sA[(c4 * 4 + 2) * 64 + row] = v.z;
            sA[(c4 * 4 + 3) * 64 + row] = v.w;
        }
    }
    __syncthreads();

    int tx = tid & 15;   // col group: cols tx*8..+7
    int ty = tid >> 4;   // row group: rows ty*4..+3

    float acc[4][8];
#pragma unroll
    for (int i = 0; i < 4; i++)
#pragma unroll
        for (int j = 0; j < 8; j++) acc[i][j] = 0.f;

#pragma unroll 8
    for (int k = 0; k < DD; k++) {
        float4 a  = *(const float4*)&sA[k * 64 + ty * 4];
        float4 b0 = *(const float4*)&sB[k * DD + tx * 8];
        float4 b1 = *(const float4*)&sB[k * DD + tx * 8 + 4];
        float av[4] = {a.x, a.y, a.z, a.w};
        float bv[8] = {b0.x, b0.y, b0.z, b0.w, b1.x, b1.y, b1.z, b1.w};
#pragma unroll
        for (int i = 0; i < 4; i++)
#pragma unroll
            for (int j = 0; j < 8; j++) acc[i][j] += av[i] * bv[j];
    }

    // epilogue
    int col0 = tx * 8;
    float bi[8], sc[8], sh[8];
#pragma unroll
    for (int j = 0; j < 8; j++) {
        bi[j] = bias[col0 + j];
        if (EPI == 1) {
            float inv = rsqrtf(rvar[col0 + j] + 1e-5f);
            sc[j] = gamma[col0 + j] * inv;
            sh[j] = beta[col0 + j] - rmean[col0 + j] * sc[j];
        }
    }
    int row0 = base + ty * 4;
#pragma unroll
    for (int i = 0; i < 4; i++) {
        int row = row0 + i;
        if (row < M) {
            float v[8];
#pragma unroll
            for (int j = 0; j < 8; j++) {
                float t = acc[i][j] + bi[j];
                t = fmaxf(t, 0.f);
                if (EPI == 1) t = t * sc[j] + sh[j];
                v[j] = t;
            }
            float4* o = (float4*)&out[(size_t)row * DD + col0];
            o[0] = make_float4(v[0], v[1], v[2], v[3]);
            o[1] = make_float4(v[4], v[5], v[6], v[7]);
        }
    }
}

// ---------------- global mean pool (batch sorted -> contiguous segments) ----------------
__global__ void k_pool(const float* __restrict__ h) {
    int g = blockIdx.x;
    int t = threadIdx.x;  // 128 threads = one feature each
    int s = g_goff[g], e = g_goff[g + 1];
    float a0 = 0.f, a1 = 0.f, a2 = 0.f, a3 = 0.f;
    int i = s;
    for (; i + 3 < e; i += 4) {
        a0 += h[(size_t)(i + 0) * DD + t];
        a1 += h[(size_t)(i + 1) * DD + t];
        a2 += h[(size_t)(i + 2) * DD + t];
        a3 += h[(size_t)(i + 3) * DD + t];
    }
    for (; i < e; i++) a0 += h[(size_t)i * DD + t];
    float cnt = (float)((e - s) > 0 ? (e - s) : 1);
    g_pool[g * DD + t] = (a0 + a1 + a2 + a3) / cnt;
}

// ---------------- launch ----------------
extern "C" void kernel_launch(void* const* d_in, const int* in_sizes, int n_in,
                              void* d_out, int out_size) {
    const float* x     = (const float*)d_in[0];
    const int*   ei    = (const int*)d_in[1];
    const int*   batch = (const int*)d_in[2];
    const float* W1    = (const float*)d_in[3];
    const float* b1    = (const float*)d_in[4];
    const float* W2    = (const float*)d_in[5];
    const float* b2    = (const float*)d_in[6];
    const float* gamma = (const float*)d_in[7];
    const float* beta  = (const float*)d_in[8];
    const float* rmean = (const float*)d_in[9];
    const float* rvar  = (const float*)d_in[10];
    const float* eps   = (const float*)d_in[11];
    const float* linW  = (const float*)d_in[12];
    const float* linb  = (const float*)d_in[13];
    float* out = (float*)d_out;

    const int* src = ei;
    const int* dst = ei + EE;

    float *ph, *pa, *pb, *ppool;
    cudaGetSymbolAddress((void**)&ph, g_h);
    cudaGetSymbolAddress((void**)&pa, g_bufA);
    cudaGetSymbolAddress((void**)&pb, g_bufB);
    cudaGetSymbolAddress((void**)&ppool, g_pool);

    cudaFuncSetAttribute(k_gemm<0>, cudaFuncAttributeMaxDynamicSharedMemorySize, GEMM_SMEM);
    cudaFuncSetAttribute(k_gemm<1>, cudaFuncAttributeMaxDynamicSharedMemorySize, GEMM_SMEM);

    // CSR build (by dst)
    k_zero_deg<<<(NN + 255) / 256, 256>>>();
    k_count<<<(EE + 255) / 256, 256>>>(dst);
    int nb = (NN + SCAN_B - 1) / SCAN_B;  // 196
    k_scan1<<<nb, SCAN_B>>>();
    k_scan2<<<1, 256>>>(nb);
    k_scan3<<<nb, SCAN_B>>>();
    k_fill<<<(EE + 255) / 256, 256>>>(src, dst);

    // pool offsets
    k_zero_gcnt<<<1, 512>>>();
    k_count_batch<<<(NN + 255) / 256, 256>>>(batch);
    k_scan_g<<<1, GG>>>();

    const float* hin = x;
    int gemm_blocks = (NN + 63) / 64;
    for (int l = 0; l < LL; l++) {
        k_agg<<<NN / 8, 256>>>(hin, eps, l, pa);
        k_gemm<0><<<gemm_blocks, 256, GEMM_SMEM>>>(pa, W1 + l * DD * DD, b1 + l * DD,
                                                   nullptr, nullptr, nullptr, nullptr, pb, NN);
        k_gemm<1><<<gemm_blocks, 256, GEMM_SMEM>>>(pb, W2 + l * DD * DD, b2 + l * DD,
                                                   gamma + l * DD, beta + l * DD,
                                                   rmean + l * DD, rvar + l * DD, ph, NN);
        hin = ph;
    }

    k_pool<<<GG, DD>>>(ph);
    k_gemm<0><<<(GG + 63) / 64, 256, GEMM_SMEM>>>(ppool, linW, linb,
                                                  nullptr, nullptr, nullptr, nullptr, out, GG);
}

// round 3
// speedup vs baseline: 1.9899x; 1.9899x over previous
#include <cuda_runtime.h>
#include <cuda_bf16.h>
#include <cstdint>

#define NN 100000
#define EE 1600000
#define DD 128
#define LL 3
#define GG 512
#define MTILES ((NN + 127) / 128)   // 782

// ---------------- scratch (device globals; no allocation allowed) ----------------
__device__ float          g_h[NN * DD];         // fp32 h (BN output, agg input)
__device__ __nv_bfloat16  g_ah[NN * DD];        // agg out hi   (gemm1 A)
__device__ __nv_bfloat16  g_al[NN * DD];        // agg out lo
__device__ __nv_bfloat16  g_bh[NN * DD];        // gemm1 out hi (gemm2 A)
__device__ __nv_bfloat16  g_bl[NN * DD];        // gemm1 out lo
__device__ __nv_bfloat16  g_wh[7 * DD * DD];    // weights hi, transposed [n][k]
__device__ __nv_bfloat16  g_wl[7 * DD * DD];    // weights lo, transposed [n][k]
__device__ __nv_bfloat16  g_ph[GG * DD];        // pooled hi
__device__ __nv_bfloat16  g_pl[GG * DD];        // pooled lo
__device__ int   g_deg[NN];
__device__ int   g_rowptr[NN + 1];
__device__ int   g_cursor[NN];
__device__ int   g_colidx[EE];
__device__ int   g_bsums[512];
__device__ int   g_gcnt[GG];
__device__ int   g_goff[GG + 1];

// ---------------- PTX helpers ----------------
__device__ __forceinline__ uint32_t smem_u32(const void* p) {
    uint32_t a;
    asm("{ .reg .u64 t; cvta.to.shared.u64 t, %1; cvt.u32.u64 %0, t; }" : "=r"(a) : "l"(p));
    return a;
}
__device__ __forceinline__ void ldsm_x4(uint32_t* r, uint32_t addr) {
    asm volatile("ldmatrix.sync.aligned.m8n8.x4.shared.b16 {%0,%1,%2,%3}, [%4];"
        : "=r"(r[0]), "=r"(r[1]), "=r"(r[2]), "=r"(r[3]) : "r"(addr));
}
__device__ __forceinline__ void mma16816(float* c, const uint32_t* a, const uint32_t* b) {
    asm volatile("mma.sync.aligned.m16n8k16.row.col.f32.bf16.bf16.f32 "
        "{%0,%1,%2,%3}, {%4,%5,%6,%7}, {%8,%9}, {%0,%1,%2,%3};"
        : "+f"(c[0]), "+f"(c[1]), "+f"(c[2]), "+f"(c[3])
        : "r"(a[0]), "r"(a[1]), "r"(a[2]), "r"(a[3]), "r"(b[0]), "r"(b[1]));
}

// ---------------- CSR build ----------------
__global__ void k_zero_deg() {
    int i = blockIdx.x * blockDim.x + threadIdx.x;
    if (i < NN) g_deg[i] = 0;
}
__global__ void k_count(const int* __restrict__ dst) {
    int e = blockIdx.x * blockDim.x + threadIdx.x;
    if (e < EE) atomicAdd(&g_deg[dst[e]], 1);
}
#define SCAN_B 512
__global__ void k_scan1() {
    __shared__ int tmp[SCAN_B];
    int t = threadIdx.x;
    int g = blockIdx.x * SCAN_B + t;
    int v = (g < NN) ? g_deg[g] : 0;
    tmp[t] = v;
    __syncthreads();
    for (int off = 1; off < SCAN_B; off <<= 1) {
        int add = (t >= off) ? tmp[t - off] : 0;
        __syncthreads();
        tmp[t] += add;
        __syncthreads();
    }
    if (g < NN) g_rowptr[g] = tmp[t] - v;
    if (t == SCAN_B - 1) g_bsums[blockIdx.x] = tmp[t];
}
__global__ void k_scan2(int nb) {
    __shared__ int tmp[256];
    int t = threadIdx.x;
    int v = (t < nb) ? g_bsums[t] : 0;
    tmp[t] = v;
    __syncthreads();
    for (int off = 1; off < 256; off <<= 1) {
        int add = (t >= off) ? tmp[t - off] : 0;
        __syncthreads();
        tmp[t] += add;
        __syncthreads();
    }
    if (t < nb) g_bsums[t] = tmp[t] - v;
}
__global__ void k_scan3() {
    int t = threadIdx.x;
    int g = blockIdx.x * SCAN_B + t;
    if (g < NN) {
        int val = g_rowptr[g] + g_bsums[blockIdx.x];
        g_rowptr[g] = val;
        g_cursor[g] = val;
        if (g == 0) g_rowptr[NN] = EE;
    }
}
__global__ void k_fill(const int* __restrict__ src, const int* __restrict__ dst) {
    int e = blockIdx.x * blockDim.x + threadIdx.x;
    if (e < EE) {
        int d = dst[e];
        int pos = atomicAdd(&g_cursor[d], 1);
        g_colidx[pos] = src[e];
    }
}
// ---------------- graph (pool) offsets ----------------
__global__ void k_zero_gcnt() { if (threadIdx.x < GG) g_gcnt[threadIdx.x] = 0; }
__global__ void k_count_batch(const int* __restrict__ batch) {
    int i = blockIdx.x * blockDim.x + threadIdx.x;
    if (i < NN) atomicAdd(&g_gcnt[batch[i]], 1);
}
__global__ void k_scan_g() {
    __shared__ int tmp[GG];
    int t = threadIdx.x;
    int v = g_gcnt[t];
    tmp[t] = v;
    __syncthreads();
    for (int off = 1; off < GG; off <<= 1) {
        int add = (t >= off) ? tmp[t - off] : 0;
        __syncthreads();
        tmp[t] += add;
        __syncthreads();
    }
    g_goff[t] = tmp[t] - v;
    if (t == GG - 1) g_goff[GG] = tmp[t];
}

// ---------------- weight preconvert: split to bf16 hi/lo, transpose to [n][k] ----------------
__global__ void k_wconv(const float* __restrict__ W1, const float* __restrict__ W2,
                        const float* __restrict__ linW) {
    int i = blockIdx.x * 256 + threadIdx.x;
    if (i >= 7 * DD * DD) return;
    int m = i >> 14, r = i & 16383;
    int k = r >> 7, n = r & 127;
    const float* src = (m < 3) ? (W1 + m * DD * DD) : ((m < 6) ? (W2 + (m - 3) * DD * DD) : linW);
    float v = src[k * DD + n];
    __nv_bfloat16 h = __float2bfloat16(v);
    float lo = v - __bfloat162float(h);
    g_wh[m * DD * DD + n * DD + k] = h;
    g_wl[m * DD * DD + n * DD + k] = __float2bfloat16(lo);
}

// ---------------- GIN aggregate + combine, split-bf16 output ----------------
__global__ void k_agg(const float* __restrict__ h, const float* __restrict__ eps,
                      int layer, __nv_bfloat16* __restrict__ oh, __nv_bfloat16* __restrict__ ol) {
    int w = (blockIdx.x * blockDim.x + threadIdx.x) >> 5;
    if (w >= NN) return;
    int lane = threadIdx.x & 31;
    float epsv = 1.0f + __ldg(&eps[layer]);
    const float4* hp = (const float4*)h;
    float4 self = hp[(size_t)w * 32 + lane];
    float ax = self.x * epsv, ay = self.y * epsv, az = self.z * epsv, aw = self.w * epsv;
    int s = g_rowptr[w], e = g_rowptr[w + 1];
    int j = s;
    for (; j + 3 < e; j += 4) {
        int s0 = g_colidx[j], s1 = g_colidx[j + 1], s2 = g_colidx[j + 2], s3 = g_colidx[j + 3];
        float4 v0 = hp[(size_t)s0 * 32 + lane];
        float4 v1 = hp[(size_t)s1 * 32 + lane];
        float4 v2 = hp[(size_t)s2 * 32 + lane];
        float4 v3 = hp[(size_t)s3 * 32 + lane];
        ax += v0.x + v1.x + v2.x + v3.x;
        ay += v0.y + v1.y + v2.y + v3.y;
        az += v0.z + v1.z + v2.z + v3.z;
        aw += v0.w + v1.w + v2.w + v3.w;
    }
    for (; j < e; j++) {
        int s0 = g_colidx[j];
        float4 v = hp[(size_t)s0 * 32 + lane];
        ax += v.x; ay += v.y; az += v.z; aw += v.w;
    }
    float vals[4] = {ax, ay, az, aw};
    __nv_bfloat16 hi[4], lo[4];
#pragma unroll
    for (int q = 0; q < 4; q++) {
        hi[q] = __float2bfloat16(vals[q]);
        lo[q] = __float2bfloat16(vals[q] - __bfloat162float(hi[q]));
    }
    size_t base = (size_t)w * DD + lane * 4;
    __nv_bfloat162 h01; h01.x = hi[0]; h01.y = hi[1];
    __nv_bfloat162 h23; h23.x = hi[2]; h23.y = hi[3];
    __nv_bfloat162 l01; l01.x = lo[0]; l01.y = lo[1];
    __nv_bfloat162 l23; l23.x = lo[2]; l23.y = lo[3];
    *(__nv_bfloat162*)(oh + base) = h01;
    *(__nv_bfloat162*)(oh + base + 2) = h23;
    *(__nv_bfloat162*)(ol + base) = l01;
    *(__nv_bfloat162*)(ol + base + 2) = l23;
}

// ---------------- mma.sync GEMM: D = epi(A @ W + bias), tile 128x128x128 ----------------
// A: bf16 hi/lo split, row-major [M][128]. W: bf16 hi/lo split, transposed [n][k].
// 8 warps: warp_m = wid&1 (64 rows), warp_n = wid>>1 (32 cols). Frags m16n8k16.
// EPI 0: relu(.+bias)   EPI 1: bn(relu(.+bias))
// OUTM 0: fp32 out      OUTM 1: bf16 hi/lo split out
#define ROWB 272            // padded row stride in bytes (136 bf16)
#define SM_AH 1536
#define SM_AL (SM_AH + 128 * ROWB)
#define SM_WH (SM_AL + 128 * ROWB)
#define SM_WL (SM_WH + 128 * ROWB)
#define SMEM_T (SM_WL + 128 * ROWB)

template <int EPI, int OUTM>
__global__ void __launch_bounds__(256, 1)
k_mma_gemm(const __nv_bfloat16* __restrict__ Ah, const __nv_bfloat16* __restrict__ Al,
           const __nv_bfloat16* __restrict__ Wh, const __nv_bfloat16* __restrict__ Wl,
           const float* __restrict__ bias,
           const float* __restrict__ gamma, const float* __restrict__ beta,
           const float* __restrict__ rmean, const float* __restrict__ rvar,
           float* __restrict__ outF, __nv_bfloat16* __restrict__ outH,
           __nv_bfloat16* __restrict__ outL, int M) {
    extern __shared__ char smem[];
    uint32_t sb = smem_u32(smem);
    int tid = threadIdx.x;
    int wid = tid >> 5;
    int lane = tid & 31;
    int base = blockIdx.x * 128;

    float* s_bias = (float*)(smem + 0);
    float* s_sc   = (float*)(smem + 512);
    float* s_sh   = (float*)(smem + 1024);

    if (tid < 128) {
        s_bias[tid] = bias[tid];
        if (EPI == 1) {
            float inv = rsqrtf(rvar[tid] + 1e-5f);
            float sc = gamma[tid] * inv;
            s_sc[tid] = sc;
            s_sh[tid] = beta[tid] - rmean[tid] * sc;
        }
    }

    // stage A hi/lo (zero-padded past M) and W hi/lo into padded row-major smem
    for (int c = tid; c < 2048; c += 256) {
        int row = c >> 4, kc = c & 15;
        uint32_t off = (uint32_t)(row * ROWB + kc * 16);
        int grow = base + row;
        uint4 vh, vl;
        if (grow < M) {
            vh = *(const uint4*)(Ah + (size_t)grow * DD + kc * 8);
            vl = *(const uint4*)(Al + (size_t)grow * DD + kc * 8);
        } else {
            vh = make_uint4(0, 0, 0, 0);
            vl = vh;
        }
        *(uint4*)(smem + SM_AH + off) = vh;
        *(uint4*)(smem + SM_AL + off) = vl;
        *(uint4*)(smem + SM_WH + off) = *(const uint4*)(Wh + (size_t)row * DD + kc * 8);
        *(uint4*)(smem + SM_WL + off) = *(const uint4*)(Wl + (size_t)row * DD + kc * 8);
    }
    __syncthreads();

    int warp_m = wid & 1;    // 0..1 -> 64 rows
    int warp_n = wid >> 1;   // 0..3 -> 32 cols

    // ldmatrix lane address components
    int q = lane >> 3;           // 0..3 (matrix index within x4)
    int l7 = lane & 7;
    // A frag x4: matrices {rows0-7,k0-7},{rows8-15,k0-7},{rows0-7,k8-15},{rows8-15,k8-15}
    uint32_t a_row = (uint32_t)(warp_m * 64 + (q & 1) * 8 + l7);
    uint32_t a_cb  = (uint32_t)((q >> 1) * 16);
    // B frag x4 (two n-frags): {n0-7,k0-7},{n0-7,k8-15},{n8-15,k0-7},{n8-15,k8-15}
    uint32_t b_row = (uint32_t)(warp_n * 32 + (q >> 1) * 8 + l7);
    uint32_t b_cb  = (uint32_t)((q & 1) * 16);

    float acc[4][4][4];
#pragma unroll
    for (int mi = 0; mi < 4; mi++)
#pragma unroll
        for (int ni = 0; ni < 4; ni++)
#pragma unroll
            for (int r = 0; r < 4; r++) acc[mi][ni][r] = 0.f;

#pragma unroll
    for (int ks = 0; ks < 8; ks++) {
        uint32_t kb = ks * 32;
        uint32_t ah[4][4], al[4][4], bh[4][2], bl[4][2];
#pragma unroll
        for (int mi = 0; mi < 4; mi++) {
            uint32_t off = (a_row + mi * 16) * ROWB + kb + a_cb;
            ldsm_x4(ah[mi], sb + SM_AH + off);
            ldsm_x4(al[mi], sb + SM_AL + off);
        }
#pragma unroll
        for (int p = 0; p < 2; p++) {
            uint32_t off = (b_row + p * 16) * ROWB + kb + b_cb;
            uint32_t th[4], tl[4];
            ldsm_x4(th, sb + SM_WH + off);
            ldsm_x4(tl, sb + SM_WL + off);
            bh[p * 2][0] = th[0]; bh[p * 2][1] = th[1];
            bh[p * 2 + 1][0] = th[2]; bh[p * 2 + 1][1] = th[3];
            bl[p * 2][0] = tl[0]; bl[p * 2][1] = tl[1];
            bl[p * 2 + 1][0] = tl[2]; bl[p * 2 + 1][1] = tl[3];
        }
#pragma unroll
        for (int mi = 0; mi < 4; mi++)
#pragma unroll
            for (int ni = 0; ni < 4; ni++) {
                mma16816(acc[mi][ni], ah[mi], bh[ni]);
                mma16816(acc[mi][ni], al[mi], bh[ni]);
                mma16816(acc[mi][ni], ah[mi], bl[ni]);
            }
    }

    // epilogue: frag (mi,ni): rows base+warp_m*64+mi*16+{l/4, l/4+8},
    //           cols warp_n*32+ni*8+(l%4)*2+{0,1}
    int l4 = lane >> 2, lm = lane & 3;
#pragma unroll
    for (int mi = 0; mi < 4; mi++) {
        int r0 = base + warp_m * 64 + mi * 16 + l4;
#pragma unroll
        for (int ni = 0; ni < 4; ni++) {
            int c0 = warp_n * 32 + ni * 8 + lm * 2;
            float b0 = s_bias[c0], b1 = s_bias[c0 + 1];
            float sc0 = 0.f, sc1 = 0.f, sh0 = 0.f, sh1 = 0.f;
            if (EPI == 1) { sc0 = s_sc[c0]; sc1 = s_sc[c0 + 1]; sh0 = s_sh[c0]; sh1 = s_sh[c0 + 1]; }
#pragma unroll
            for (int half = 0; half < 2; half++) {
                int row = r0 + half * 8;
                if (row < M) {
                    float v0 = fmaxf(acc[mi][ni][half * 2] + b0, 0.f);
                    float v1 = fmaxf(acc[mi][ni][half * 2 + 1] + b1, 0.f);
                    if (EPI == 1) { v0 = v0 * sc0 + sh0; v1 = v1 * sc1 + sh1; }
                    if (OUTM == 0) {
                        *(float2*)(outF + (size_t)row * DD + c0) = make_float2(v0, v1);
                    } else {
                        __nv_bfloat162 h2, l2;
                        h2.x = __float2bfloat16(v0);
                        h2.y = __float2bfloat16(v1);
                        l2.x = __float2bfloat16(v0 - __bfloat162float(h2.x));
                        l2.y = __float2bfloat16(v1 - __bfloat162float(h2.y));
                        *(__nv_bfloat162*)(outH + (size_t)row * DD + c0) = h2;
                        *(__nv_bfloat162*)(outL + (size_t)row * DD + c0) = l2;
                    }
                }
            }
        }
    }
}

// ---------------- global mean pool -> split bf16 ----------------
__global__ void k_pool(const float* __restrict__ h) {
    int g = blockIdx.x;
    int t = threadIdx.x;
    int s = g_goff[g], e = g_goff[g + 1];
    float a0 = 0.f, a1 = 0.f, a2 = 0.f, a3 = 0.f;
    int i = s;
    for (; i + 3 < e; i += 4) {
        a0 += h[(size_t)(i + 0) * DD + t];
        a1 += h[(size_t)(i + 1) * DD + t];
        a2 += h[(size_t)(i + 2) * DD + t];
        a3 += h[(size_t)(i + 3) * DD + t];
    }
    for (; i < e; i++) a0 += h[(size_t)i * DD + t];
    float cnt = (float)((e - s) > 0 ? (e - s) : 1);
    float v = (a0 + a1 + a2 + a3) / cnt;
    __nv_bfloat16 hi = __float2bfloat16(v);
    g_ph[g * DD + t] = hi;
    g_pl[g * DD + t] = __float2bfloat16(v - __bfloat162float(hi));
}

// ---------------- launch ----------------
extern "C" void kernel_launch(void* const* d_in, const int* in_sizes, int n_in,
                              void* d_out, int out_size) {
    const float* x     = (const float*)d_in[0];
    const int*   ei    = (const int*)d_in[1];
    const int*   batch = (const int*)d_in[2];
    const float* W1    = (const float*)d_in[3];
    const float* b1    = (const float*)d_in[4];
    const float* W2    = (const float*)d_in[5];
    const float* b2    = (const float*)d_in[6];
    const float* gamma = (const float*)d_in[7];
    const float* beta  = (const float*)d_in[8];
    const float* rmean = (const float*)d_in[9];
    const float* rvar  = (const float*)d_in[10];
    const float* eps   = (const float*)d_in[11];
    const float* linW  = (const float*)d_in[12];
    const float* linb  = (const float*)d_in[13];
    float* out = (float*)d_out;

    const int* src = ei;
    const int* dst = ei + EE;

    float* ph;
    __nv_bfloat16 *pah, *pal, *pbh, *pbl, *pwh, *pwl, *pph, *ppl;
    cudaGetSymbolAddress((void**)&ph,  g_h);
    cudaGetSymbolAddress((void**)&pah, g_ah);
    cudaGetSymbolAddress((void**)&pal, g_al);
    cudaGetSymbolAddress((void**)&pbh, g_bh);
    cudaGetSymbolAddress((void**)&pbl, g_bl);
    cudaGetSymbolAddress((void**)&pwh, g_wh);
    cudaGetSymbolAddress((void**)&pwl, g_wl);
    cudaGetSymbolAddress((void**)&pph, g_ph);
    cudaGetSymbolAddress((void**)&ppl, g_pl);

    cudaFuncSetAttribute(k_mma_gemm<0, 1>, cudaFuncAttributeMaxDynamicSharedMemorySize, SMEM_T);
    cudaFuncSetAttribute(k_mma_gemm<1, 0>, cudaFuncAttributeMaxDynamicSharedMemorySize, SMEM_T);
    cudaFuncSetAttribute(k_mma_gemm<0, 0>, cudaFuncAttributeMaxDynamicSharedMemorySize, SMEM_T);

    // weights: split + transpose (7 matrices)
    k_wconv<<<(7 * DD * DD + 255) / 256, 256>>>(W1, W2, linW);

    // CSR build (by dst)
    k_zero_deg<<<(NN + 255) / 256, 256>>>();
    k_count<<<(EE + 255) / 256, 256>>>(dst);
    int nb = (NN + SCAN_B - 1) / SCAN_B;
    k_scan1<<<nb, SCAN_B>>>();
    k_scan2<<<1, 256>>>(nb);
    k_scan3<<<nb, SCAN_B>>>();
    k_fill<<<(EE + 255) / 256, 256>>>(src, dst);

    // pool offsets
    k_zero_gcnt<<<1, 512>>>();
    k_count_batch<<<(NN + 255) / 256, 256>>>(batch);
    k_scan_g<<<1, GG>>>();

    const float* hin = x;
    for (int l = 0; l < LL; l++) {
        k_agg<<<NN / 8, 256>>>(hin, eps, l, pah, pal);
        k_mma_gemm<0, 1><<<MTILES, 256, SMEM_T>>>(pah, pal,
                pwh + l * DD * DD, pwl + l * DD * DD, b1 + l * DD,
                nullptr, nullptr, nullptr, nullptr,
                nullptr, pbh, pbl, NN);
        k_mma_gemm<1, 0><<<MTILES, 256, SMEM_T>>>(pbh, pbl,
                pwh + (3 + l) * DD * DD, pwl + (3 + l) * DD * DD, b2 + l * DD,
                gamma + l * DD, beta + l * DD, rmean + l * DD, rvar + l * DD,
                ph, nullptr, nullptr, NN);
        hin = ph;
    }

    k_pool<<<GG, DD>>>(ph);
    k_mma_gemm<0, 0><<<(GG + 127) / 128, 256, SMEM_T>>>(pph, ppl,
            pwh + 6 * DD * DD, pwl + 6 * DD * DD, linb,
            nullptr, nullptr, nullptr, nullptr,
            out, nullptr, nullptr, GG);
}

// round 4
// speedup vs baseline: 2.1463x; 1.0786x over previous
#include <cuda_runtime.h>
#include <cuda_bf16.h>
#include <cuda_fp16.h>
#include <cstdint>

#define NN 100000
#define EE 1600000
#define DD 128
#define LL 3
#define GG 512
#define MTILES ((NN + 127) / 128)   // 782

// ---------------- scratch (device globals; no allocation allowed) ----------------
__device__ __half         g_hx[NN * DD];        // h (and x) in fp16: agg gather source
__device__ __nv_bfloat16  g_ah[NN * DD];        // agg out hi   (gemm1 A)
__device__ __nv_bfloat16  g_al[NN * DD];        // agg out lo
__device__ __nv_bfloat16  g_bh[NN * DD];        // gemm1 out hi (gemm2 A)
__device__ __nv_bfloat16  g_bl[NN * DD];        // gemm1 out lo
__device__ __nv_bfloat16  g_wh[7 * DD * DD];    // weights hi, transposed [n][k]
__device__ __nv_bfloat16  g_wl[7 * DD * DD];    // weights lo, transposed [n][k]
__device__ __nv_bfloat16  g_ph[GG * DD];        // pooled hi
__device__ __nv_bfloat16  g_pl[GG * DD];        // pooled lo
__device__ int   g_deg[NN];
__device__ int   g_rowptr[NN + 1];
__device__ int   g_cursor[NN];
__device__ int   g_colidx[EE];
__device__ int   g_bsums[512];
__device__ int   g_gcnt[GG];
__device__ int   g_goff[GG + 1];

// ---------------- PTX helpers ----------------
__device__ __forceinline__ uint32_t smem_u32(const void* p) {
    uint32_t a;
    asm("{ .reg .u64 t; cvta.to.shared.u64 t, %1; cvt.u32.u64 %0, t; }" : "=r"(a) : "l"(p));
    return a;
}
__device__ __forceinline__ void ldsm_x4(uint32_t* r, uint32_t addr) {
    asm volatile("ldmatrix.sync.aligned.m8n8.x4.shared.b16 {%0,%1,%2,%3}, [%4];"
        : "=r"(r[0]), "=r"(r[1]), "=r"(r[2]), "=r"(r[3]) : "r"(addr));
}
__device__ __forceinline__ void mma16816(float* c, const uint32_t* a, const uint32_t* b) {
    asm volatile("mma.sync.aligned.m16n8k16.row.col.f32.bf16.bf16.f32 "
        "{%0,%1,%2,%3}, {%4,%5,%6,%7}, {%8,%9}, {%0,%1,%2,%3};"
        : "+f"(c[0]), "+f"(c[1]), "+f"(c[2]), "+f"(c[3])
        : "r"(a[0]), "r"(a[1]), "r"(a[2]), "r"(a[3]), "r"(b[0]), "r"(b[1]));
}

// ---------------- CSR build ----------------
__global__ void k_zero_deg() {
    int i = blockIdx.x * blockDim.x + threadIdx.x;
    if (i < NN) g_deg[i] = 0;
}
__global__ void k_count(const int* __restrict__ dst) {
    int e = blockIdx.x * blockDim.x + threadIdx.x;
    if (e < EE) atomicAdd(&g_deg[dst[e]], 1);
}
#define SCAN_B 512
__global__ void k_scan1() {
    __shared__ int tmp[SCAN_B];
    int t = threadIdx.x;
    int g = blockIdx.x * SCAN_B + t;
    int v = (g < NN) ? g_deg[g] : 0;
    tmp[t] = v;
    __syncthreads();
    for (int off = 1; off < SCAN_B; off <<= 1) {
        int add = (t >= off) ? tmp[t - off] : 0;
        __syncthreads();
        tmp[t] += add;
        __syncthreads();
    }
    if (g < NN) g_rowptr[g] = tmp[t] - v;
    if (t == SCAN_B - 1) g_bsums[blockIdx.x] = tmp[t];
}
__global__ void k_scan2(int nb) {
    __shared__ int tmp[256];
    int t = threadIdx.x;
    int v = (t < nb) ? g_bsums[t] : 0;
    tmp[t] = v;
    __syncthreads();
    for (int off = 1; off < 256; off <<= 1) {
        int add = (t >= off) ? tmp[t - off] : 0;
        __syncthreads();
        tmp[t] += add;
        __syncthreads();
    }
    if (t < nb) g_bsums[t] = tmp[t] - v;
}
__global__ void k_scan3() {
    int t = threadIdx.x;
    int g = blockIdx.x * SCAN_B + t;
    if (g < NN) {
        int val = g_rowptr[g] + g_bsums[blockIdx.x];
        g_rowptr[g] = val;
        g_cursor[g] = val;
        if (g == 0) g_rowptr[NN] = EE;
    }
}
__global__ void k_fill(const int* __restrict__ src, const int* __restrict__ dst) {
    int e = blockIdx.x * blockDim.x + threadIdx.x;
    if (e < EE) {
        int d = dst[e];
        int pos = atomicAdd(&g_cursor[d], 1);
        g_colidx[pos] = src[e];
    }
}
// ---------------- graph (pool) offsets ----------------
__global__ void k_zero_gcnt() { if (threadIdx.x < GG) g_gcnt[threadIdx.x] = 0; }
__global__ void k_count_batch(const int* __restrict__ batch) {
    int i = blockIdx.x * blockDim.x + threadIdx.x;
    if (i < NN) atomicAdd(&g_gcnt[batch[i]], 1);
}
__global__ void k_scan_g() {
    __shared__ int tmp[GG];
    int t = threadIdx.x;
    int v = g_gcnt[t];
    tmp[t] = v;
    __syncthreads();
    for (int off = 1; off < GG; off <<= 1) {
        int add = (t >= off) ? tmp[t - off] : 0;
        __syncthreads();
        tmp[t] += add;
        __syncthreads();
    }
    g_goff[t] = tmp[t] - v;
    if (t == GG - 1) g_goff[GG] = tmp[t];
}

// ---------------- x -> fp16 convert ----------------
__global__ void k_xconv(const float* __restrict__ x) {
    int i = blockIdx.x * 256 + threadIdx.x;   // one float4 -> half4 per thread
    if (i >= NN * DD / 4) return;
    float4 v = ((const float4*)x)[i];
    __half2 a = __floats2half2_rn(v.x, v.y);
    __half2 b = __floats2half2_rn(v.z, v.w);
    uint32_t pa = *(uint32_t*)&a, pb = *(uint32_t*)&b;
    ((uint2*)g_hx)[i] = make_uint2(pa, pb);
}

// ---------------- weight preconvert: split to bf16 hi/lo, transpose to [n][k] ----------------
__global__ void k_wconv(const float* __restrict__ W1, const float* __restrict__ W2,
                        const float* __restrict__ linW) {
    int i = blockIdx.x * 256 + threadIdx.x;
    if (i >= 7 * DD * DD) return;
    int m = i >> 14, r = i & 16383;
    int k = r >> 7, n = r & 127;
    const float* src = (m < 3) ? (W1 + m * DD * DD) : ((m < 6) ? (W2 + (m - 3) * DD * DD) : linW);
    float v = src[k * DD + n];
    __nv_bfloat16 h = __float2bfloat16(v);
    float lo = v - __bfloat162float(h);
    g_wh[m * DD * DD + n * DD + k] = h;
    g_wl[m * DD * DD + n * DD + k] = __float2bfloat16(lo);
}

// ---------------- GIN aggregate + combine (fp16 gather), split-bf16 output ----------------
__global__ void k_agg(const float* __restrict__ eps, int layer,
                      __nv_bfloat16* __restrict__ oh, __nv_bfloat16* __restrict__ ol) {
    int w = (blockIdx.x * blockDim.x + threadIdx.x) >> 5;
    if (w >= NN) return;
    int lane = threadIdx.x & 31;
    float epsv = 1.0f + __ldg(&eps[layer]);
    const uint2* hp = (const uint2*)g_hx;   // 4 halves per uint2, 32 uint2 per row
    uint2 sv = hp[(size_t)w * 32 + lane];
    float2 s01 = __half22float2(*(__half2*)&sv.x);
    float2 s23 = __half22float2(*(__half2*)&sv.y);
    float ax = s01.x * epsv, ay = s01.y * epsv, az = s23.x * epsv, aw = s23.y * epsv;
    int s = g_rowptr[w], e = g_rowptr[w + 1];
    int j = s;
    for (; j + 3 < e; j += 4) {
        int s0 = g_colidx[j], s1 = g_colidx[j + 1], s2 = g_colidx[j + 2], s3 = g_colidx[j + 3];
        uint2 v0 = hp[(size_t)s0 * 32 + lane];
        uint2 v1 = hp[(size_t)s1 * 32 + lane];
        uint2 v2 = hp[(size_t)s2 * 32 + lane];
        uint2 v3 = hp[(size_t)s3 * 32 + lane];
        float2 a0 = __half22float2(*(__half2*)&v0.x), b0 = __half22float2(*(__half2*)&v0.y);
        float2 a1 = __half22float2(*(__half2*)&v1.x), b1 = __half22float2(*(__half2*)&v1.y);
        float2 a2 = __half22float2(*(__half2*)&v2.x), b2 = __half22float2(*(__half2*)&v2.y);
        float2 a3 = __half22float2(*(__half2*)&v3.x), b3 = __half22float2(*(__half2*)&v3.y);
        ax += a0.x + a1.x + a2.x + a3.x;
        ay += a0.y + a1.y + a2.y + a3.y;
        az += b0.x + b1.x + b2.x + b3.x;
        aw += b0.y + b1.y + b2.y + b3.y;
    }
    for (; j < e; j++) {
        int s0 = g_colidx[j];
        uint2 v = hp[(size_t)s0 * 32 + lane];
        float2 a = __half22float2(*(__half2*)&v.x), b = __half22float2(*(__half2*)&v.y);
        ax += a.x; ay += a.y; az += b.x; aw += b.y;
    }
    float vals[4] = {ax, ay, az, aw};
    __nv_bfloat16 hi[4], lo[4];
#pragma unroll
    for (int q = 0; q < 4; q++) {
        hi[q] = __float2bfloat16(vals[q]);
        lo[q] = __float2bfloat16(vals[q] - __bfloat162float(hi[q]));
    }
    size_t base = (size_t)w * DD + lane * 4;
    __nv_bfloat162 h01; h01.x = hi[0]; h01.y = hi[1];
    __nv_bfloat162 h23; h23.x = hi[2]; h23.y = hi[3];
    __nv_bfloat162 l01; l01.x = lo[0]; l01.y = lo[1];
    __nv_bfloat162 l23; l23.x = lo[2]; l23.y = lo[3];
    *(__nv_bfloat162*)(oh + base) = h01;
    *(__nv_bfloat162*)(oh + base + 2) = h23;
    *(__nv_bfloat162*)(ol + base) = l01;
    *(__nv_bfloat162*)(ol + base + 2) = l23;
}

// ---------------- mma.sync GEMM: D = epi(A @ W + bias), tile 128x128x128 ----------------
// EPI 0: relu(.+bias)   EPI 1: bn(relu(.+bias))
// OUTM 0: fp32 out      OUTM 1: bf16 hi/lo split out    OUTM 2: fp16 out
#define ROWB 272            // padded row stride in bytes (136 bf16)
#define SM_AH 1536
#define SM_AL (SM_AH + 128 * ROWB)
#define SM_WH (SM_AL + 128 * ROWB)
#define SM_WL (SM_WH + 128 * ROWB)
#define SMEM_T (SM_WL + 128 * ROWB)

template <int EPI, int OUTM>
__global__ void __launch_bounds__(256, 1)
k_mma_gemm(const __nv_bfloat16* __restrict__ Ah, const __nv_bfloat16* __restrict__ Al,
           const __nv_bfloat16* __restrict__ Wh, const __nv_bfloat16* __restrict__ Wl,
           const float* __restrict__ bias,
           const float* __restrict__ gamma, const float* __restrict__ beta,
           const float* __restrict__ rmean, const float* __restrict__ rvar,
           float* __restrict__ outF, __nv_bfloat16* __restrict__ outH,
           __nv_bfloat16* __restrict__ outL, __half* __restrict__ outX, int M) {
    extern __shared__ char smem[];
    uint32_t sb = smem_u32(smem);
    int tid = threadIdx.x;
    int wid = tid >> 5;
    int lane = tid & 31;
    int base = blockIdx.x * 128;

    float* s_bias = (float*)(smem + 0);
    float* s_sc   = (float*)(smem + 512);
    float* s_sh   = (float*)(smem + 1024);

    if (tid < 128) {
        s_bias[tid] = bias[tid];
        if (EPI == 1) {
            float inv = rsqrtf(rvar[tid] + 1e-5f);
            float sc = gamma[tid] * inv;
            s_sc[tid] = sc;
            s_sh[tid] = beta[tid] - rmean[tid] * sc;
        }
    }

    for (int c = tid; c < 2048; c += 256) {
        int row = c >> 4, kc = c & 15;
        uint32_t off = (uint32_t)(row * ROWB + kc * 16);
        int grow = base + row;
        uint4 vh, vl;
        if (grow < M) {
            vh = *(const uint4*)(Ah + (size_t)grow * DD + kc * 8);
            vl = *(const uint4*)(Al + (size_t)grow * DD + kc * 8);
        } else {
            vh = make_uint4(0, 0, 0, 0);
            vl = vh;
        }
        *(uint4*)(smem + SM_AH + off) = vh;
        *(uint4*)(smem + SM_AL + off) = vl;
        *(uint4*)(smem + SM_WH + off) = *(const uint4*)(Wh + (size_t)row * DD + kc * 8);
        *(uint4*)(smem + SM_WL + off) = *(const uint4*)(Wl + (size_t)row * DD + kc * 8);
    }
    __syncthreads();

    int warp_m = wid & 1;    // 0..1 -> 64 rows
    int warp_n = wid >> 1;   // 0..3 -> 32 cols

    int q = lane >> 3;
    int l7 = lane & 7;
    uint32_t a_row = (uint32_t)(warp_m * 64 + (q & 1) * 8 + l7);
    uint32_t a_cb  = (uint32_t)((q >> 1) * 16);
    uint32_t b_row = (uint32_t)(warp_n * 32 + (q >> 1) * 8 + l7);
    uint32_t b_cb  = (uint32_t)((q & 1) * 16);

    float acc[4][4][4];
#pragma unroll
    for (int mi = 0; mi < 4; mi++)
#pragma unroll
        for (int ni = 0; ni < 4; ni++)
#pragma unroll
            for (int r = 0; r < 4; r++) acc[mi][ni][r] = 0.f;

#pragma unroll
    for (int ks = 0; ks < 8; ks++) {
        uint32_t kb = ks * 32;
        uint32_t ah[4][4], al[4][4], bh[4][2], bl[4][2];
#pragma unroll
        for (int mi = 0; mi < 4; mi++) {
            uint32_t off = (a_row + mi * 16) * ROWB + kb + a_cb;
            ldsm_x4(ah[mi], sb + SM_AH + off);
            ldsm_x4(al[mi], sb + SM_AL + off);
        }
#pragma unroll
        for (int p = 0; p < 2; p++) {
            uint32_t off = (b_row + p * 16) * ROWB + kb + b_cb;
            uint32_t th[4], tl[4];
            ldsm_x4(th, sb + SM_WH + off);
            ldsm_x4(tl, sb + SM_WL + off);
            bh[p * 2][0] = th[0]; bh[p * 2][1] = th[1];
            bh[p * 2 + 1][0] = th[2]; bh[p * 2 + 1][1] = th[3];
            bl[p * 2][0] = tl[0]; bl[p * 2][1] = tl[1];
            bl[p * 2 + 1][0] = tl[2]; bl[p * 2 + 1][1] = tl[3];
        }
#pragma unroll
        for (int mi = 0; mi < 4; mi++)
#pragma unroll
            for (int ni = 0; ni < 4; ni++) {
                mma16816(acc[mi][ni], ah[mi], bh[ni]);
                mma16816(acc[mi][ni], al[mi], bh[ni]);
                mma16816(acc[mi][ni], ah[mi], bl[ni]);
            }
    }

    int l4 = lane >> 2, lm = lane & 3;
#pragma unroll
    for (int mi = 0; mi < 4; mi++) {
        int r0 = base + warp_m * 64 + mi * 16 + l4;
#pragma unroll
        for (int ni = 0; ni < 4; ni++) {
            int c0 = warp_n * 32 + ni * 8 + lm * 2;
            float b0 = s_bias[c0], b1 = s_bias[c0 + 1];
            float sc0 = 0.f, sc1 = 0.f, sh0 = 0.f, sh1 = 0.f;
            if (EPI == 1) { sc0 = s_sc[c0]; sc1 = s_sc[c0 + 1]; sh0 = s_sh[c0]; sh1 = s_sh[c0 + 1]; }
#pragma unroll
            for (int half = 0; half < 2; half++) {
                int row = r0 + half * 8;
                if (row < M) {
                    float v0 = fmaxf(acc[mi][ni][half * 2] + b0, 0.f);
                    float v1 = fmaxf(acc[mi][ni][half * 2 + 1] + b1, 0.f);
                    if (EPI == 1) { v0 = v0 * sc0 + sh0; v1 = v1 * sc1 + sh1; }
                    if (OUTM == 0) {
                        *(float2*)(outF + (size_t)row * DD + c0) = make_float2(v0, v1);
                    } else if (OUTM == 1) {
                        __nv_bfloat162 h2, l2;
                        h2.x = __float2bfloat16(v0);
                        h2.y = __float2bfloat16(v1);
                        l2.x = __float2bfloat16(v0 - __bfloat162float(h2.x));
                        l2.y = __float2bfloat16(v1 - __bfloat162float(h2.y));
                        *(__nv_bfloat162*)(outH + (size_t)row * DD + c0) = h2;
                        *(__nv_bfloat162*)(outL + (size_t)row * DD + c0) = l2;
                    } else {
                        __half2 x2 = __floats2half2_rn(v0, v1);
                        *(__half2*)(outX + (size_t)row * DD + c0) = x2;
                    }
                }
            }
        }
    }
}

// ---------------- global mean pool (fp16 in) -> split bf16 ----------------
__global__ void k_pool() {
    int g = blockIdx.x;
    int t = threadIdx.x;
    int s = g_goff[g], e = g_goff[g + 1];
    float a0 = 0.f, a1 = 0.f, a2 = 0.f, a3 = 0.f;
    int i = s;
    for (; i + 3 < e; i += 4) {
        a0 += __half2float(g_hx[(size_t)(i + 0) * DD + t]);
        a1 += __half2float(g_hx[(size_t)(i + 1) * DD + t]);
        a2 += __half2float(g_hx[(size_t)(i + 2) * DD + t]);
        a3 += __half2float(g_hx[(size_t)(i + 3) * DD + t]);
    }
    for (; i < e; i++) a0 += __half2float(g_hx[(size_t)i * DD + t]);
    float cnt = (float)((e - s) > 0 ? (e - s) : 1);
    float v = (a0 + a1 + a2 + a3) / cnt;
    __nv_bfloat16 hi = __float2bfloat16(v);
    g_ph[g * DD + t] = hi;
    g_pl[g * DD + t] = __float2bfloat16(v - __bfloat162float(hi));
}

// ---------------- launch ----------------
extern "C" void kernel_launch(void* const* d_in, const int* in_sizes, int n_in,
                              void* d_out, int out_size) {
    const float* x     = (const float*)d_in[0];
    const int*   ei    = (const int*)d_in[1];
    const int*   batch = (const int*)d_in[2];
    const float* W1    = (const float*)d_in[3];
    const float* b1    = (const float*)d_in[4];
    const float* W2    = (const float*)d_in[5];
    const float* b2    = (const float*)d_in[6];
    const float* gamma = (const float*)d_in[7];
    const float* beta  = (const float*)d_in[8];
    const float* rmean = (const float*)d_in[9];
    const float* rvar  = (const float*)d_in[10];
    const float* eps   = (const float*)d_in[11];
    const float* linW  = (const float*)d_in[12];
    const float* linb  = (const float*)d_in[13];
    float* out = (float*)d_out;

    const int* src = ei;
    const int* dst = ei + EE;

    __half* phx;
    __nv_bfloat16 *pah, *pal, *pbh, *pbl, *pwh, *pwl, *pph, *ppl;
    cudaGetSymbolAddress((void**)&phx, g_hx);
    cudaGetSymbolAddress((void**)&pah, g_ah);
    cudaGetSymbolAddress((void**)&pal, g_al);
    cudaGetSymbolAddress((void**)&pbh, g_bh);
    cudaGetSymbolAddress((void**)&pbl, g_bl);
    cudaGetSymbolAddress((void**)&pwh, g_wh);
    cudaGetSymbolAddress((void**)&pwl, g_wl);
    cudaGetSymbolAddress((void**)&pph, g_ph);
    cudaGetSymbolAddress((void**)&ppl, g_pl);

    cudaFuncSetAttribute(k_mma_gemm<0, 1>, cudaFuncAttributeMaxDynamicSharedMemorySize, SMEM_T);
    cudaFuncSetAttribute(k_mma_gemm<1, 2>, cudaFuncAttributeMaxDynamicSharedMemorySize, SMEM_T);
    cudaFuncSetAttribute(k_mma_gemm<0, 0>, cudaFuncAttributeMaxDynamicSharedMemorySize, SMEM_T);

    k_wconv<<<(7 * DD * DD + 255) / 256, 256>>>(W1, W2, linW);
    k_xconv<<<(NN * DD / 4 + 255) / 256, 256>>>(x);

    // CSR build (by dst)
    k_zero_deg<<<(NN + 255) / 256, 256>>>();
    k_count<<<(EE + 255) / 256, 256>>>(dst);
    int nb = (NN + SCAN_B - 1) / SCAN_B;
    k_scan1<<<nb, SCAN_B>>>();
    k_scan2<<<1, 256>>>(nb);
    k_scan3<<<nb, SCAN_B>>>();
    k_fill<<<(EE + 255) / 256, 256>>>(src, dst);

    // pool offsets
    k_zero_gcnt<<<1, 512>>>();
    k_count_batch<<<(NN + 255) / 256, 256>>>(batch);
    k_scan_g<<<1, GG>>>();

    for (int l = 0; l < LL; l++) {
        k_agg<<<NN / 8, 256>>>(eps, l, pah, pal);
        k_mma_gemm<0, 1><<<MTILES, 256, SMEM_T>>>(pah, pal,
                pwh + l * DD * DD, pwl + l * DD * DD, b1 + l * DD,
                nullptr, nullptr, nullptr, nullptr,
                nullptr, pbh, pbl, nullptr, NN);
        k_mma_gemm<1, 2><<<MTILES, 256, SMEM_T>>>(pbh, pbl,
                pwh + (3 + l) * DD * DD, pwl + (3 + l) * DD * DD, b2 + l * DD,
                gamma + l * DD, beta + l * DD, rmean + l * DD, rvar + l * DD,
                nullptr, nullptr, nullptr, phx, NN);
    }

    k_pool<<<GG, DD>>>();
    k_mma_gemm<0, 0><<<(GG + 127) / 128, 256, SMEM_T>>>(pph, ppl,
            pwh + 6 * DD * DD, pwl + 6 * DD * DD, linb,
            nullptr, nullptr, nullptr, nullptr,
            out, nullptr, nullptr, nullptr, GG);
}

// round 5
// speedup vs baseline: 3.2430x; 1.5110x over previous
#include <cuda_runtime.h>
#include <cuda_fp16.h>
#include <cstdint>

#define NN 100000
#define EE 1600000
#define DD 128
#define LL 3
#define GG 512
#define MTILES ((NN + 127) / 128)   // 782

// ---------------- scratch (device globals; no allocation allowed) ----------------
__device__ __half g_hx[NN * DD];        // h (and x) in fp16: agg gather source / layer output
__device__ __half g_af[NN * DD];        // agg output (layer GEMM A operand)
__device__ __half g_wh[7 * DD * DD];    // weights hi (fp16), transposed [n][k]
__device__ __half g_wl[7 * DD * DD];    // weights lo (fp16 residual), transposed [n][k]
__device__ __half g_pf[GG * DD];        // pooled (fp16)
__device__ int   g_deg[NN];
__device__ int   g_rowptr[NN + 1];
__device__ int   g_cursor[NN];
__device__ int   g_colidx[EE];
__device__ int   g_bsums[512];
__device__ int   g_gcnt[GG];
__device__ int   g_goff[GG + 1];

// ---------------- PTX helpers ----------------
__device__ __forceinline__ uint32_t smem_u32(const void* p) {
    uint32_t a;
    asm("{ .reg .u64 t; cvta.to.shared.u64 t, %1; cvt.u32.u64 %0, t; }" : "=r"(a) : "l"(p));
    return a;
}
__device__ __forceinline__ void ldsm_x4(uint32_t* r, uint32_t addr) {
    asm volatile("ldmatrix.sync.aligned.m8n8.x4.shared.b16 {%0,%1,%2,%3}, [%4];"
        : "=r"(r[0]), "=r"(r[1]), "=r"(r[2]), "=r"(r[3]) : "r"(addr));
}
__device__ __forceinline__ void mma16816h(float* c, const uint32_t* a, const uint32_t* b) {
    asm volatile("mma.sync.aligned.m16n8k16.row.col.f32.f16.f16.f32 "
        "{%0,%1,%2,%3}, {%4,%5,%6,%7}, {%8,%9}, {%0,%1,%2,%3};"
        : "+f"(c[0]), "+f"(c[1]), "+f"(c[2]), "+f"(c[3])
        : "r"(a[0]), "r"(a[1]), "r"(a[2]), "r"(a[3]), "r"(b[0]), "r"(b[1]));
}

// ---------------- CSR + pool-offset build ----------------
__global__ void k_zero() {
    int i = blockIdx.x * blockDim.x + threadIdx.x;
    if (i < NN) g_deg[i] = 0;
    if (i < GG) g_gcnt[i] = 0;
}
__global__ void k_counts(const int* __restrict__ dst, const int* __restrict__ batch) {
    int e = blockIdx.x * blockDim.x + threadIdx.x;
    if (e < EE) atomicAdd(&g_deg[dst[e]], 1);
    if (e < NN) atomicAdd(&g_gcnt[batch[e]], 1);
}
#define SCAN_B 512
__global__ void k_scan1() {
    __shared__ int tmp[SCAN_B];
    int t = threadIdx.x;
    int g = blockIdx.x * SCAN_B + t;
    int v = (g < NN) ? g_deg[g] : 0;
    tmp[t] = v;
    __syncthreads();
    for (int off = 1; off < SCAN_B; off <<= 1) {
        int add = (t >= off) ? tmp[t - off] : 0;
        __syncthreads();
        tmp[t] += add;
        __syncthreads();
    }
    if (g < NN) g_rowptr[g] = tmp[t] - v;
    if (t == SCAN_B - 1) g_bsums[blockIdx.x] = tmp[t];
}
__global__ void k_scan2(int nb) {
    __shared__ int tmp[256];
    int t = threadIdx.x;
    int v = (t < nb) ? g_bsums[t] : 0;
    tmp[t] = v;
    __syncthreads();
    for (int off = 1; off < 256; off <<= 1) {
        int add = (t >= off) ? tmp[t - off] : 0;
        __syncthreads();
        tmp[t] += add;
        __syncthreads();
    }
    if (t < nb) g_bsums[t] = tmp[t] - v;
}
__global__ void k_scan3() {
    int t = threadIdx.x;
    int g = blockIdx.x * SCAN_B + t;
    if (g < NN) {
        int val = g_rowptr[g] + g_bsums[blockIdx.x];
        g_rowptr[g] = val;
        g_cursor[g] = val;
        if (g == 0) g_rowptr[NN] = EE;
    }
}
__global__ void k_fill(const int* __restrict__ src, const int* __restrict__ dst) {
    int e = blockIdx.x * blockDim.x + threadIdx.x;
    if (e < EE) {
        int d = dst[e];
        int pos = atomicAdd(&g_cursor[d], 1);
        g_colidx[pos] = src[e];
    }
}
__global__ void k_scan_g() {
    __shared__ int tmp[GG];
    int t = threadIdx.x;
    int v = g_gcnt[t];
    tmp[t] = v;
    __syncthreads();
    for (int off = 1; off < GG; off <<= 1) {
        int add = (t >= off) ? tmp[t - off] : 0;
        __syncthreads();
        tmp[t] += add;
        __syncthreads();
    }
    g_goff[t] = tmp[t] - v;
    if (t == GG - 1) g_goff[GG] = tmp[t];
}

// ---------------- x -> fp16 convert ----------------
__global__ void k_xconv(const float* __restrict__ x) {
    int i = blockIdx.x * 256 + threadIdx.x;
    if (i >= NN * DD / 4) return;
    float4 v = ((const float4*)x)[i];
    __half2 a = __floats2half2_rn(v.x, v.y);
    __half2 b = __floats2half2_rn(v.z, v.w);
    ((uint2*)g_hx)[i] = make_uint2(*(uint32_t*)&a, *(uint32_t*)&b);
}

// ---------------- weight preconvert: split to fp16 hi/lo, transpose to [n][k] ----------------
__global__ void k_wconv(const float* __restrict__ W1, const float* __restrict__ W2,
                        const float* __restrict__ linW) {
    int i = blockIdx.x * 256 + threadIdx.x;
    if (i >= 7 * DD * DD) return;
    int m = i >> 14, r = i & 16383;
    int k = r >> 7, n = r & 127;
    const float* src = (m < 3) ? (W1 + m * DD * DD) : ((m < 6) ? (W2 + (m - 3) * DD * DD) : linW);
    float v = src[k * DD + n];
    __half h = __float2half_rn(v);
    float lo = v - __half2float(h);
    g_wh[m * DD * DD + n * DD + k] = h;
    g_wl[m * DD * DD + n * DD + k] = __float2half_rn(lo);
}

// ---------------- GIN aggregate + combine (fp16 gather -> fp16 out) ----------------
__global__ void k_agg(const float* __restrict__ eps, int layer) {
    int w = (blockIdx.x * blockDim.x + threadIdx.x) >> 5;
    if (w >= NN) return;
    int lane = threadIdx.x & 31;
    float epsv = 1.0f + __ldg(&eps[layer]);
    const uint2* hp = (const uint2*)g_hx;
    uint2 sv = hp[(size_t)w * 32 + lane];
    float2 s01 = __half22float2(*(__half2*)&sv.x);
    float2 s23 = __half22float2(*(__half2*)&sv.y);
    float ax = s01.x * epsv, ay = s01.y * epsv, az = s23.x * epsv, aw = s23.y * epsv;
    int s = g_rowptr[w], e = g_rowptr[w + 1];
    int j = s;
    for (; j + 3 < e; j += 4) {
        int s0 = g_colidx[j], s1 = g_colidx[j + 1], s2 = g_colidx[j + 2], s3 = g_colidx[j + 3];
        uint2 v0 = hp[(size_t)s0 * 32 + lane];
        uint2 v1 = hp[(size_t)s1 * 32 + lane];
        uint2 v2 = hp[(size_t)s2 * 32 + lane];
        uint2 v3 = hp[(size_t)s3 * 32 + lane];
        float2 a0 = __half22float2(*(__half2*)&v0.x), b0 = __half22float2(*(__half2*)&v0.y);
        float2 a1 = __half22float2(*(__half2*)&v1.x), b1 = __half22float2(*(__half2*)&v1.y);
        float2 a2 = __half22float2(*(__half2*)&v2.x), b2 = __half22float2(*(__half2*)&v2.y);
        float2 a3 = __half22float2(*(__half2*)&v3.x), b3 = __half22float2(*(__half2*)&v3.y);
        ax += a0.x + a1.x + a2.x + a3.x;
        ay += a0.y + a1.y + a2.y + a3.y;
        az += b0.x + b1.x + b2.x + b3.x;
        aw += b0.y + b1.y + b2.y + b3.y;
    }
    for (; j < e; j++) {
        int s0 = g_colidx[j];
        uint2 v = hp[(size_t)s0 * 32 + lane];
        float2 a = __half22float2(*(__half2*)&v.x), b = __half22float2(*(__half2*)&v.y);
        ax += a.x; ay += a.y; az += b.x; aw += b.y;
    }
    __half2 p0 = __floats2half2_rn(ax, ay);
    __half2 p1 = __floats2half2_rn(az, aw);
    ((uint2*)g_af)[(size_t)w * 32 + lane] = make_uint2(*(uint32_t*)&p0, *(uint32_t*)&p1);
}

// ---------------- shared GEMM tile core (128x128x128, 2-product fp16) ----------------
#define ROWB 272            // padded row stride in bytes (136 halves)
#define BUFB (128 * ROWB)   // 34816

__device__ __forceinline__ void gemm_tile(uint32_t sb, uint32_t smA, uint32_t smWh, uint32_t smWl,
                                          int wid, int lane, float acc[4][4][4]) {
    int warp_m = wid & 1;
    int warp_n = wid >> 1;
    int q = lane >> 3, l7 = lane & 7;
    uint32_t a_row = (uint32_t)(warp_m * 64 + (q & 1) * 8 + l7);
    uint32_t a_cb  = (uint32_t)((q >> 1) * 16);
    uint32_t b_row = (uint32_t)(warp_n * 32 + (q >> 1) * 8 + l7);
    uint32_t b_cb  = (uint32_t)((q & 1) * 16);
#pragma unroll
    for (int ks = 0; ks < 8; ks++) {
        uint32_t kb = ks * 32;
        uint32_t ah[4][4], bh[4][2], bl[4][2];
#pragma unroll
        for (int mi = 0; mi < 4; mi++)
            ldsm_x4(ah[mi], sb + smA + (a_row + mi * 16) * ROWB + kb + a_cb);
#pragma unroll
        for (int p = 0; p < 2; p++) {
            uint32_t off = (b_row + p * 16) * ROWB + kb + b_cb;
            uint32_t th[4], tl[4];
            ldsm_x4(th, sb + smWh + off);
            ldsm_x4(tl, sb + smWl + off);
            bh[p * 2][0] = th[0]; bh[p * 2][1] = th[1];
            bh[p * 2 + 1][0] = th[2]; bh[p * 2 + 1][1] = th[3];
            bl[p * 2][0] = tl[0]; bl[p * 2][1] = tl[1];
            bl[p * 2 + 1][0] = tl[2]; bl[p * 2 + 1][1] = tl[3];
        }
#pragma unroll
        for (int mi = 0; mi < 4; mi++)
#pragma unroll
            for (int ni = 0; ni < 4; ni++) {
                mma16816h(acc[mi][ni], ah[mi], bh[ni]);
                mma16816h(acc[mi][ni], ah[mi], bl[ni]);
            }
    }
}

// ---------------- fused layer kernel: h = BN(relu(relu(A@W1+b1)@W2+b2)) ----------------
#define SM_A   1536
#define SM_Z   (SM_A + BUFB)
#define SM_W1H (SM_Z + BUFB)
#define SM_W1L (SM_W1H + BUFB)
#define SM_W2H (SM_W1L + BUFB)
#define SM_W2L (SM_W2H + BUFB)
#define SMEM_F (SM_W2L + BUFB)    // 210432

__global__ void __launch_bounds__(256, 1)
k_layer(const __half* __restrict__ A,
        const __half* __restrict__ W1h, const __half* __restrict__ W1l,
        const __half* __restrict__ W2h, const __half* __restrict__ W2l,
        const float* __restrict__ b1, const float* __restrict__ b2,
        const float* __restrict__ gamma, const float* __restrict__ beta,
        const float* __restrict__ rmean, const float* __restrict__ rvar, int M) {
    extern __shared__ char smem[];
    uint32_t sb = smem_u32(smem);
    int tid = threadIdx.x;
    int wid = tid >> 5;
    int lane = tid & 31;
    int base = blockIdx.x * 128;

    float* s_b1 = (float*)(smem + 0);
    float* s_b2 = (float*)(smem + 512);
    float* s_sc = (float*)(smem + 1024);
    // s_sh packed after s_sc would exceed 1536; fold shift into registers instead per-thread.

    if (tid < 128) {
        s_b1[tid] = b1[tid];
        s_b2[tid] = b2[tid];
        float inv = rsqrtf(rvar[tid] + 1e-5f);
        s_sc[tid] = gamma[tid] * inv;   // scale; shift recomputed in epilogue from beta/rmean
    }

    // stage A + 4 weight buffers
    for (int c = tid; c < 2048; c += 256) {
        int row = c >> 4, kc = c & 15;
        uint32_t off = (uint32_t)(row * ROWB + kc * 16);
        int grow = base + row;
        uint4 va = make_uint4(0, 0, 0, 0);
        if (grow < M) va = *(const uint4*)(A + (size_t)grow * DD + kc * 8);
        *(uint4*)(smem + SM_A + off) = va;
        size_t woff = (size_t)row * DD + kc * 8;
        *(uint4*)(smem + SM_W1H + off) = *(const uint4*)(W1h + woff);
        *(uint4*)(smem + SM_W1L + off) = *(const uint4*)(W1l + woff);
        *(uint4*)(smem + SM_W2H + off) = *(const uint4*)(W2h + woff);
        *(uint4*)(smem + SM_W2L + off) = *(const uint4*)(W2l + woff);
    }
    __syncthreads();

    float acc[4][4][4];
#pragma unroll
    for (int mi = 0; mi < 4; mi++)
#pragma unroll
        for (int ni = 0; ni < 4; ni++)
#pragma unroll
            for (int r = 0; r < 4; r++) acc[mi][ni][r] = 0.f;

    // GEMM1
    gemm_tile(sb, SM_A, SM_W1H, SM_W1L, wid, lane, acc);

    // epilogue1: relu(.+b1) -> sZ (fp16). Bank pattern 4*l4+lm is a perfect permutation.
    int warp_m = wid & 1, warp_n = wid >> 1;
    int l4 = lane >> 2, lm = lane & 3;
    __syncthreads();   // ensure no warp still ldsm-ing A region? (A untouched; this syncs Z reuse ordering)
#pragma unroll
    for (int mi = 0; mi < 4; mi++) {
        int rloc = warp_m * 64 + mi * 16 + l4;
#pragma unroll
        for (int ni = 0; ni < 4; ni++) {
            int c0 = warp_n * 32 + ni * 8 + lm * 2;
            float bb0 = s_b1[c0], bb1 = s_b1[c0 + 1];
#pragma unroll
            for (int half = 0; half < 2; half++) {
                float v0 = fmaxf(acc[mi][ni][half * 2] + bb0, 0.f);
                float v1 = fmaxf(acc[mi][ni][half * 2 + 1] + bb1, 0.f);
                __half2 z2 = __floats2half2_rn(v0, v1);
                *(__half2*)(smem + SM_Z + (rloc + half * 8) * ROWB + c0 * 2) = z2;
            }
        }
    }
    __syncthreads();

#pragma unroll
    for (int mi = 0; mi < 4; mi++)
#pragma unroll
        for (int ni = 0; ni < 4; ni++)
#pragma unroll
            for (int r = 0; r < 4; r++) acc[mi][ni][r] = 0.f;

    // GEMM2
    gemm_tile(sb, SM_Z, SM_W2H, SM_W2L, wid, lane, acc);

    // epilogue2: BN(relu(.+b2)) -> global fp16 h
#pragma unroll
    for (int mi = 0; mi < 4; mi++) {
        int r0 = base + warp_m * 64 + mi * 16 + l4;
#pragma unroll
        for (int ni = 0; ni < 4; ni++) {
            int c0 = warp_n * 32 + ni * 8 + lm * 2;
            float bb0 = s_b2[c0], bb1 = s_b2[c0 + 1];
            float sc0 = s_sc[c0], sc1 = s_sc[c0 + 1];
            float sh0 = beta[c0] - rmean[c0] * sc0;
            float sh1 = beta[c0 + 1] - rmean[c0 + 1] * sc1;
#pragma unroll
            for (int half = 0; half < 2; half++) {
                int row = r0 + half * 8;
                if (row < M) {
                    float v0 = fmaxf(acc[mi][ni][half * 2] + bb0, 0.f) * sc0 + sh0;
                    float v1 = fmaxf(acc[mi][ni][half * 2 + 1] + bb1, 0.f) * sc1 + sh1;
                    __half2 x2 = __floats2half2_rn(v0, v1);
                    *(__half2*)(g_hx + (size_t)row * DD + c0) = x2;
                }
            }
        }
    }
}

// ---------------- lin1 kernel: out = relu(pooled @ W + b), fp32 out ----------------
#define SM_LWH (SM_A + BUFB)
#define SM_LWL (SM_LWH + BUFB)
#define SMEM_L (SM_LWL + BUFB)   // ~106 KB

__global__ void __launch_bounds__(256, 1)
k_lin(const __half* __restrict__ Wh, const __half* __restrict__ Wl,
      const float* __restrict__ bias, float* __restrict__ out, int M) {
    extern __shared__ char smem[];
    uint32_t sb = smem_u32(smem);
    int tid = threadIdx.x;
    int wid = tid >> 5;
    int lane = tid & 31;
    int base = blockIdx.x * 128;

    float* s_bias = (float*)(smem + 0);
    if (tid < 128) s_bias[tid] = bias[tid];

    for (int c = tid; c < 2048; c += 256) {
        int row = c >> 4, kc = c & 15;
        uint32_t off = (uint32_t)(row * ROWB + kc * 16);
        int grow = base + row;
        uint4 va = make_uint4(0, 0, 0, 0);
        if (grow < M) va = *(const uint4*)(g_pf + (size_t)grow * DD + kc * 8);
        *(uint4*)(smem + SM_A + off) = va;
        size_t woff = (size_t)row * DD + kc * 8;
        *(uint4*)(smem + SM_LWH + off) = *(const uint4*)(Wh + woff);
        *(uint4*)(smem + SM_LWL + off) = *(const uint4*)(Wl + woff);
    }
    __syncthreads();

    float acc[4][4][4];
#pragma unroll
    for (int mi = 0; mi < 4; mi++)
#pragma unroll
        for (int ni = 0; ni < 4; ni++)
#pragma unroll
            for (int r = 0; r < 4; r++) acc[mi][ni][r] = 0.f;

    gemm_tile(sb, SM_A, SM_LWH, SM_LWL, wid, lane, acc);

    int warp_m = wid & 1, warp_n = wid >> 1;
    int l4 = lane >> 2, lm = lane & 3;
#pragma unroll
    for (int mi = 0; mi < 4; mi++) {
        int r0 = base + warp_m * 64 + mi * 16 + l4;
#pragma unroll
        for (int ni = 0; ni < 4; ni++) {
            int c0 = warp_n * 32 + ni * 8 + lm * 2;
            float bb0 = s_bias[c0], bb1 = s_bias[c0 + 1];
#pragma unroll
            for (int half = 0; half < 2; half++) {
                int row = r0 + half * 8;
                if (row < M) {
                    float v0 = fmaxf(acc[mi][ni][half * 2] + bb0, 0.f);
                    float v1 = fmaxf(acc[mi][ni][half * 2 + 1] + bb1, 0.f);
                    *(float2*)(out + (size_t)row * DD + c0) = make_float2(v0, v1);
                }
            }
        }
    }
}

// ---------------- global mean pool (fp16 in -> fp16 out) ----------------
__global__ void k_pool() {
    int g = blockIdx.x;
    int t = threadIdx.x;
    int s = g_goff[g], e = g_goff[g + 1];
    float a0 = 0.f, a1 = 0.f, a2 = 0.f, a3 = 0.f;
    int i = s;
    for (; i + 3 < e; i += 4) {
        a0 += __half2float(g_hx[(size_t)(i + 0) * DD + t]);
        a1 += __half2float(g_hx[(size_t)(i + 1) * DD + t]);
        a2 += __half2float(g_hx[(size_t)(i + 2) * DD + t]);
        a3 += __half2float(g_hx[(size_t)(i + 3) * DD + t]);
    }
    for (; i < e; i++) a0 += __half2float(g_hx[(size_t)i * DD + t]);
    float cnt = (float)((e - s) > 0 ? (e - s) : 1);
    g_pf[g * DD + t] = __float2half_rn((a0 + a1 + a2 + a3) / cnt);
}

// ---------------- launch ----------------
extern "C" void kernel_launch(void* const* d_in, const int* in_sizes, int n_in,
                              void* d_out, int out_size) {
    const float* x     = (const float*)d_in[0];
    const int*   ei    = (const int*)d_in[1];
    const int*   batch = (const int*)d_in[2];
    const float* W1    = (const float*)d_in[3];
    const float* b1    = (const float*)d_in[4];
    const float* W2    = (const float*)d_in[5];
    const float* b2    = (const float*)d_in[6];
    const float* gamma = (const float*)d_in[7];
    const float* beta  = (const float*)d_in[8];
    const float* rmean = (const float*)d_in[9];
    const float* rvar  = (const float*)d_in[10];
    const float* eps   = (const float*)d_in[11];
    const float* linW  = (const float*)d_in[12];
    const float* linb  = (const float*)d_in[13];
    float* out = (float*)d_out;

    const int* src = ei;
    const int* dst = ei + EE;

    __half *paf, *pwh, *pwl;
    cudaGetSymbolAddress((void**)&paf, g_af);
    cudaGetSymbolAddress((void**)&pwh, g_wh);
    cudaGetSymbolAddress((void**)&pwl, g_wl);

    cudaFuncSetAttribute(k_layer, cudaFuncAttributeMaxDynamicSharedMemorySize, SMEM_F);
    cudaFuncSetAttribute(k_lin,   cudaFuncAttributeMaxDynamicSharedMemorySize, SMEM_L);

    k_wconv<<<(7 * DD * DD + 255) / 256, 256>>>(W1, W2, linW);
    k_xconv<<<(NN * DD / 4 + 255) / 256, 256>>>(x);

    // CSR + pool offsets
    k_zero<<<(NN + 255) / 256, 256>>>();
    k_counts<<<(EE + 255) / 256, 256>>>(dst, batch);
    int nb = (NN + SCAN_B - 1) / SCAN_B;
    k_scan1<<<nb, SCAN_B>>>();
    k_scan2<<<1, 256>>>(nb);
    k_scan3<<<nb, SCAN_B>>>();
    k_fill<<<(EE + 255) / 256, 256>>>(src, dst);
    k_scan_g<<<1, GG>>>();

    for (int l = 0; l < LL; l++) {
        k_agg<<<NN / 8, 256>>>(eps, l);
        k_layer<<<MTILES, 256, SMEM_F>>>(paf,
                pwh + l * DD * DD,       pwl + l * DD * DD,
                pwh + (3 + l) * DD * DD, pwl + (3 + l) * DD * DD,
                b1 + l * DD, b2 + l * DD,
                gamma + l * DD, beta + l * DD, rmean + l * DD, rvar + l * DD, NN);
    }

    k_pool<<<GG, DD>>>();
    k_lin<<<(GG + 127) / 128, 256, SMEM_L>>>(pwh + 6 * DD * DD, pwl + 6 * DD * DD,
                                             linb, out, GG);
}

// round 6
// speedup vs baseline: 3.4001x; 1.0484x over previous
#include <cuda_runtime.h>
#include <cuda_fp16.h>
#include <cstdint>

#define NN 100000
#define EE 1600000
#define DD 128
#define LL 3
#define GG 512
#define MTILES ((NN + 127) / 128)   // 782
#define NSM 148

// ---------------- scratch (device globals; no allocation allowed) ----------------
__device__ __half g_hx[NN * DD];        // h (and x) in fp16: agg gather source / layer output
__device__ __half g_af[NN * DD];        // agg output (layer GEMM A operand)
__device__ __half g_wh[7 * DD * DD];    // weights hi (fp16), transposed [n][k]
__device__ __half g_wl[7 * DD * DD];    // weights lo (fp16 residual), transposed [n][k]
__device__ __half g_pf[GG * DD];        // pooled (fp16)
__device__ int   g_deg[NN];
__device__ int   g_rowptr[NN + 1];
__device__ int   g_cursor[NN];
__device__ int   g_colidx[EE];
__device__ int   g_bsums[512];
__device__ int   g_gcnt[GG];
__device__ int   g_goff[GG + 1];

// ---------------- PTX helpers ----------------
__device__ __forceinline__ uint32_t smem_u32(const void* p) {
    uint32_t a;
    asm("{ .reg .u64 t; cvta.to.shared.u64 t, %1; cvt.u32.u64 %0, t; }" : "=r"(a) : "l"(p));
    return a;
}
__device__ __forceinline__ void ldsm_x4(uint32_t* r, uint32_t addr) {
    asm volatile("ldmatrix.sync.aligned.m8n8.x4.shared.b16 {%0,%1,%2,%3}, [%4];"
        : "=r"(r[0]), "=r"(r[1]), "=r"(r[2]), "=r"(r[3]) : "r"(addr));
}
__device__ __forceinline__ void mma16816h(float* c, const uint32_t* a, const uint32_t* b) {
    asm volatile("mma.sync.aligned.m16n8k16.row.col.f32.f16.f16.f32 "
        "{%0,%1,%2,%3}, {%4,%5,%6,%7}, {%8,%9}, {%0,%1,%2,%3};"
        : "+f"(c[0]), "+f"(c[1]), "+f"(c[2]), "+f"(c[3])
        : "r"(a[0]), "r"(a[1]), "r"(a[2]), "r"(a[3]), "r"(b[0]), "r"(b[1]));
}

// ---------------- CSR + pool-offset build (vectorized: 4 items/thread) ----------------
__global__ void k_counts(const int* __restrict__ dst, const int* __restrict__ batch) {
    int i = blockIdx.x * blockDim.x + threadIdx.x;   // quad index
    if (i < EE / 4) {
        int4 d = ((const int4*)dst)[i];
        atomicAdd(&g_deg[d.x], 1);
        atomicAdd(&g_deg[d.y], 1);
        atomicAdd(&g_deg[d.z], 1);
        atomicAdd(&g_deg[d.w], 1);
    }
    if (i < NN / 4) {
        int4 b = ((const int4*)batch)[i];
        atomicAdd(&g_gcnt[b.x], 1);
        atomicAdd(&g_gcnt[b.y], 1);
        atomicAdd(&g_gcnt[b.z], 1);
        atomicAdd(&g_gcnt[b.w], 1);
    }
}
#define SCAN_B 512
__global__ void k_scan1() {
    __shared__ int tmp[SCAN_B];
    int t = threadIdx.x;
    int g = blockIdx.x * SCAN_B + t;
    int v = (g < NN) ? g_deg[g] : 0;
    tmp[t] = v;
    __syncthreads();
    for (int off = 1; off < SCAN_B; off <<= 1) {
        int add = (t >= off) ? tmp[t - off] : 0;
        __syncthreads();
        tmp[t] += add;
        __syncthreads();
    }
    if (g < NN) g_rowptr[g] = tmp[t] - v;
    if (t == SCAN_B - 1) g_bsums[blockIdx.x] = tmp[t];
}
__global__ void k_scan2(int nb) {
    __shared__ int tmp[256];
    int t = threadIdx.x;
    int v = (t < nb) ? g_bsums[t] : 0;
    tmp[t] = v;
    __syncthreads();
    for (int off = 1; off < 256; off <<= 1) {
        int add = (t >= off) ? tmp[t - off] : 0;
        __syncthreads();
        tmp[t] += add;
        __syncthreads();
    }
    if (t < nb) g_bsums[t] = tmp[t] - v;
}
__global__ void k_scan3() {
    int t = threadIdx.x;
    int g = blockIdx.x * SCAN_B + t;
    if (g < NN) {
        int val = g_rowptr[g] + g_bsums[blockIdx.x];
        g_rowptr[g] = val;
        g_cursor[g] = val;
        if (g == 0) g_rowptr[NN] = EE;
    }
}
__global__ void k_fill(const int* __restrict__ src, const int* __restrict__ dst) {
    int i = blockIdx.x * blockDim.x + threadIdx.x;   // quad index
    if (i >= EE / 4) return;
    int4 d = ((const int4*)dst)[i];
    int4 s = ((const int4*)src)[i];
    int p0 = atomicAdd(&g_cursor[d.x], 1);
    int p1 = atomicAdd(&g_cursor[d.y], 1);
    int p2 = atomicAdd(&g_cursor[d.z], 1);
    int p3 = atomicAdd(&g_cursor[d.w], 1);
    g_colidx[p0] = s.x;
    g_colidx[p1] = s.y;
    g_colidx[p2] = s.z;
    g_colidx[p3] = s.w;
}
__global__ void k_scan_g() {
    __shared__ int tmp[GG];
    int t = threadIdx.x;
    int v = g_gcnt[t];
    tmp[t] = v;
    __syncthreads();
    for (int off = 1; off < GG; off <<= 1) {
        int add = (t >= off) ? tmp[t - off] : 0;
        __syncthreads();
        tmp[t] += add;
        __syncthreads();
    }
    g_goff[t] = tmp[t] - v;
    if (t == GG - 1) g_goff[GG] = tmp[t];
}

// ---------------- x -> fp16 convert ----------------
__global__ void k_xconv(const float* __restrict__ x) {
    int i = blockIdx.x * 256 + threadIdx.x;
    if (i >= NN * DD / 4) return;
    float4 v = ((const float4*)x)[i];
    __half2 a = __floats2half2_rn(v.x, v.y);
    __half2 b = __floats2half2_rn(v.z, v.w);
    ((uint2*)g_hx)[i] = make_uint2(*(uint32_t*)&a, *(uint32_t*)&b);
}

// ---------------- weight preconvert: split to fp16 hi/lo, transpose to [n][k] ----------------
__global__ void k_wconv(const float* __restrict__ W1, const float* __restrict__ W2,
                        const float* __restrict__ linW) {
    int i = blockIdx.x * 256 + threadIdx.x;
    if (i >= 7 * DD * DD) return;
    int m = i >> 14, r = i & 16383;
    int k = r >> 7, n = r & 127;
    const float* src = (m < 3) ? (W1 + m * DD * DD) : ((m < 6) ? (W2 + (m - 3) * DD * DD) : linW);
    float v = src[k * DD + n];
    __half h = __float2half_rn(v);
    float lo = v - __half2float(h);
    g_wh[m * DD * DD + n * DD + k] = h;
    g_wl[m * DD * DD + n * DD + k] = __float2half_rn(lo);
}

// ---------------- GIN aggregate + combine (fp16 gather -> fp16 out) ----------------
__global__ void k_agg(const float* __restrict__ eps, int layer) {
    int w = (blockIdx.x * blockDim.x + threadIdx.x) >> 5;
    if (w >= NN) return;
    int lane = threadIdx.x & 31;
    float epsv = 1.0f + __ldg(&eps[layer]);
    const uint2* hp = (const uint2*)g_hx;
    uint2 sv = hp[(size_t)w * 32 + lane];
    float2 s01 = __half22float2(*(__half2*)&sv.x);
    float2 s23 = __half22float2(*(__half2*)&sv.y);
    float ax = s01.x * epsv, ay = s01.y * epsv, az = s23.x * epsv, aw = s23.y * epsv;
    int s = g_rowptr[w], e = g_rowptr[w + 1];
    int j = s;
    for (; j + 3 < e; j += 4) {
        int s0 = g_colidx[j], s1 = g_colidx[j + 1], s2 = g_colidx[j + 2], s3 = g_colidx[j + 3];
        uint2 v0 = hp[(size_t)s0 * 32 + lane];
        uint2 v1 = hp[(size_t)s1 * 32 + lane];
        uint2 v2 = hp[(size_t)s2 * 32 + lane];
        uint2 v3 = hp[(size_t)s3 * 32 + lane];
        float2 a0 = __half22float2(*(__half2*)&v0.x), b0 = __half22float2(*(__half2*)&v0.y);
        float2 a1 = __half22float2(*(__half2*)&v1.x), b1 = __half22float2(*(__half2*)&v1.y);
        float2 a2 = __half22float2(*(__half2*)&v2.x), b2 = __half22float2(*(__half2*)&v2.y);
        float2 a3 = __half22float2(*(__half2*)&v3.x), b3 = __half22float2(*(__half2*)&v3.y);
        ax += a0.x + a1.x + a2.x + a3.x;
        ay += a0.y + a1.y + a2.y + a3.y;
        az += b0.x + b1.x + b2.x + b3.x;
        aw += b0.y + b1.y + b2.y + b3.y;
    }
    for (; j < e; j++) {
        int s0 = g_colidx[j];
        uint2 v = hp[(size_t)s0 * 32 + lane];
        float2 a = __half22float2(*(__half2*)&v.x), b = __half22float2(*(__half2*)&v.y);
        ax += a.x; ay += a.y; az += b.x; aw += b.y;
    }
    __half2 p0 = __floats2half2_rn(ax, ay);
    __half2 p1 = __floats2half2_rn(az, aw);
    ((uint2*)g_af)[(size_t)w * 32 + lane] = make_uint2(*(uint32_t*)&p0, *(uint32_t*)&p1);
}

// ---------------- shared GEMM tile core (128x128x128, 2-product fp16) ----------------
#define ROWB 272            // padded row stride in bytes (136 halves)
#define BUFB (128 * ROWB)   // 34816

__device__ __forceinline__ void gemm_tile(uint32_t sb, uint32_t smA, uint32_t smWh, uint32_t smWl,
                                          int wid, int lane, float acc[4][4][4]) {
    int warp_m = wid & 1;
    int warp_n = wid >> 1;
    int q = lane >> 3, l7 = lane & 7;
    uint32_t a_row = (uint32_t)(warp_m * 64 + (q & 1) * 8 + l7);
    uint32_t a_cb  = (uint32_t)((q >> 1) * 16);
    uint32_t b_row = (uint32_t)(warp_n * 32 + (q >> 1) * 8 + l7);
    uint32_t b_cb  = (uint32_t)((q & 1) * 16);
#pragma unroll
    for (int ks = 0; ks < 8; ks++) {
        uint32_t kb = ks * 32;
        uint32_t ah[4][4], bh[4][2], bl[4][2];
#pragma unroll
        for (int mi = 0; mi < 4; mi++)
            ldsm_x4(ah[mi], sb + smA + (a_row + mi * 16) * ROWB + kb + a_cb);
#pragma unroll
        for (int p = 0; p < 2; p++) {
            uint32_t off = (b_row + p * 16) * ROWB + kb + b_cb;
            uint32_t th[4], tl[4];
            ldsm_x4(th, sb + smWh + off);
            ldsm_x4(tl, sb + smWl + off);
            bh[p * 2][0] = th[0]; bh[p * 2][1] = th[1];
            bh[p * 2 + 1][0] = th[2]; bh[p * 2 + 1][1] = th[3];
            bl[p * 2][0] = tl[0]; bl[p * 2][1] = tl[1];
            bl[p * 2 + 1][0] = tl[2]; bl[p * 2 + 1][1] = tl[3];
        }
#pragma unroll
        for (int mi = 0; mi < 4; mi++)
#pragma unroll
            for (int ni = 0; ni < 4; ni++) {
                mma16816h(acc[mi][ni], ah[mi], bh[ni]);
                mma16816h(acc[mi][ni], ah[mi], bl[ni]);
            }
    }
}

// ---------------- persistent fused layer: h = BN(relu(relu(A@W1+b1)@W2+b2)) ----------------
#define SM_A   1536
#define SM_Z   (SM_A + BUFB)
#define SM_W1H (SM_Z + BUFB)
#define SM_W1L (SM_W1H + BUFB)
#define SM_W2H (SM_W1L + BUFB)
#define SM_W2L (SM_W2H + BUFB)
#define SMEM_F (SM_W2L + BUFB)    // 210432

__global__ void __launch_bounds__(256, 1)
k_layer(const __half* __restrict__ A,
        const __half* __restrict__ W1h, const __half* __restrict__ W1l,
        const __half* __restrict__ W2h, const __half* __restrict__ W2l,
        const float* __restrict__ b1, const float* __restrict__ b2,
        const float* __restrict__ gamma, const float* __restrict__ beta,
        const float* __restrict__ rmean, const float* __restrict__ rvar, int M) {
    extern __shared__ char smem[];
    uint32_t sb = smem_u32(smem);
    int tid = threadIdx.x;
    int wid = tid >> 5;
    int lane = tid & 31;

    float* s_b1 = (float*)(smem + 0);
    float* s_b2 = (float*)(smem + 512);
    float* s_sc = (float*)(smem + 1024);

    if (tid < 128) {
        s_b1[tid] = b1[tid];
        s_b2[tid] = b2[tid];
        float inv = rsqrtf(rvar[tid] + 1e-5f);
        s_sc[tid] = gamma[tid] * inv;
    }

    // stage the 4 weight buffers ONCE
    for (int c = tid; c < 2048; c += 256) {
        int row = c >> 4, kc = c & 15;
        uint32_t off = (uint32_t)(row * ROWB + kc * 16);
        size_t woff = (size_t)row * DD + kc * 8;
        *(uint4*)(smem + SM_W1H + off) = *(const uint4*)(W1h + woff);
        *(uint4*)(smem + SM_W1L + off) = *(const uint4*)(W1l + woff);
        *(uint4*)(smem + SM_W2H + off) = *(const uint4*)(W2h + woff);
        *(uint4*)(smem + SM_W2L + off) = *(const uint4*)(W2l + woff);
    }

    int warp_m = wid & 1, warp_n = wid >> 1;
    int l4 = lane >> 2, lm = lane & 3;
    int ntiles = (M + 127) / 128;

    for (int t = blockIdx.x; t < ntiles; t += gridDim.x) {
        int base = t * 128;
        // stage A tile (A region disjoint from everything read after last sync)
        for (int c = tid; c < 2048; c += 256) {
            int row = c >> 4, kc = c & 15;
            uint32_t off = (uint32_t)(row * ROWB + kc * 16);
            int grow = base + row;
            uint4 va = make_uint4(0, 0, 0, 0);
            if (grow < M) va = *(const uint4*)(A + (size_t)grow * DD + kc * 8);
            *(uint4*)(smem + SM_A + off) = va;
        }
        __syncthreads();   // sync1: A staged (also: all warps past gemm2 of prev tile)

        float acc[4][4][4];
#pragma unroll
        for (int mi = 0; mi < 4; mi++)
#pragma unroll
            for (int ni = 0; ni < 4; ni++)
#pragma unroll
                for (int r = 0; r < 4; r++) acc[mi][ni][r] = 0.f;

        gemm_tile(sb, SM_A, SM_W1H, SM_W1L, wid, lane, acc);

        // epilogue1: relu(.+b1) -> Z (fp16)
#pragma unroll
        for (int mi = 0; mi < 4; mi++) {
            int rloc = warp_m * 64 + mi * 16 + l4;
#pragma unroll
            for (int ni = 0; ni < 4; ni++) {
                int c0 = warp_n * 32 + ni * 8 + lm * 2;
                float bb0 = s_b1[c0], bb1 = s_b1[c0 + 1];
#pragma unroll
                for (int half = 0; half < 2; half++) {
                    float v0 = fmaxf(acc[mi][ni][half * 2] + bb0, 0.f);
                    float v1 = fmaxf(acc[mi][ni][half * 2 + 1] + bb1, 0.f);
                    __half2 z2 = __floats2half2_rn(v0, v1);
                    *(__half2*)(smem + SM_Z + (rloc + half * 8) * ROWB + c0 * 2) = z2;
                }
            }
        }
        __syncthreads();   // sync2: Z complete (also: all warps past gemm1 A-reads)

#pragma unroll
        for (int mi = 0; mi < 4; mi++)
#pragma unroll
            for (int ni = 0; ni < 4; ni++)
#pragma unroll
                for (int r = 0; r < 4; r++) acc[mi][ni][r] = 0.f;

        gemm_tile(sb, SM_Z, SM_W2H, SM_W2L, wid, lane, acc);

        // epilogue2: BN(relu(.+b2)) -> global fp16 h
#pragma unroll
        for (int mi = 0; mi < 4; mi++) {
            int r0 = base + warp_m * 64 + mi * 16 + l4;
#pragma unroll
            for (int ni = 0; ni < 4; ni++) {
                int c0 = warp_n * 32 + ni * 8 + lm * 2;
                float bb0 = s_b2[c0], bb1 = s_b2[c0 + 1];
                float sc0 = s_sc[c0], sc1 = s_sc[c0 + 1];
                float sh0 = beta[c0] - rmean[c0] * sc0;
                float sh1 = beta[c0 + 1] - rmean[c0 + 1] * sc1;
#pragma unroll
                for (int half = 0; half < 2; half++) {
                    int row = r0 + half * 8;
                    if (row < M) {
                        float v0 = fmaxf(acc[mi][ni][half * 2] + bb0, 0.f) * sc0 + sh0;
                        float v1 = fmaxf(acc[mi][ni][half * 2 + 1] + bb1, 0.f) * sc1 + sh1;
                        __half2 x2 = __floats2half2_rn(v0, v1);
                        *(__half2*)(g_hx + (size_t)row * DD + c0) = x2;
                    }
                }
            }
        }
    }
}

// ---------------- lin1 kernel: out = relu(pooled @ W + b), fp32 out ----------------
#define SM_LWH (SM_A + BUFB)
#define SM_LWL (SM_LWH + BUFB)
#define SMEM_L (SM_LWL + BUFB)

__global__ void __launch_bounds__(256, 1)
k_lin(const __half* __restrict__ Wh, const __half* __restrict__ Wl,
      const float* __restrict__ bias, float* __restrict__ out, int M) {
    extern __shared__ char smem[];
    uint32_t sb = smem_u32(smem);
    int tid = threadIdx.x;
    int wid = tid >> 5;
    int lane = tid & 31;
    int base = blockIdx.x * 128;

    float* s_bias = (float*)(smem + 0);
    if (tid < 128) s_bias[tid] = bias[tid];

    for (int c = tid; c < 2048; c += 256) {
        int row = c >> 4, kc = c & 15;
        uint32_t off = (uint32_t)(row * ROWB + kc * 16);
        int grow = base + row;
        uint4 va = make_uint4(0, 0, 0, 0);
        if (grow < M) va = *(const uint4*)(g_pf + (size_t)grow * DD + kc * 8);
        *(uint4*)(smem + SM_A + off) = va;
        size_t woff = (size_t)row * DD + kc * 8;
        *(uint4*)(smem + SM_LWH + off) = *(const uint4*)(Wh + woff);
        *(uint4*)(smem + SM_LWL + off) = *(const uint4*)(Wl + woff);
    }
    __syncthreads();

    float acc[4][4][4];
#pragma unroll
    for (int mi = 0; mi < 4; mi++)
#pragma unroll
        for (int ni = 0; ni < 4; ni++)
#pragma unroll
            for (int r = 0; r < 4; r++) acc[mi][ni][r] = 0.f;

    gemm_tile(sb, SM_A, SM_LWH, SM_LWL, wid, lane, acc);

    int warp_m = wid & 1, warp_n = wid >> 1;
    int l4 = lane >> 2, lm = lane & 3;
#pragma unroll
    for (int mi = 0; mi < 4; mi++) {
        int r0 = base + warp_m * 64 + mi * 16 + l4;
#pragma unroll
        for (int ni = 0; ni < 4; ni++) {
            int c0 = warp_n * 32 + ni * 8 + lm * 2;
            float bb0 = s_bias[c0], bb1 = s_bias[c0 + 1];
#pragma unroll
            for (int half = 0; half < 2; half++) {
                int row = r0 + half * 8;
                if (row < M) {
                    float v0 = fmaxf(acc[mi][ni][half * 2] + bb0, 0.f);
                    float v1 = fmaxf(acc[mi][ni][half * 2 + 1] + bb1, 0.f);
                    *(float2*)(out + (size_t)row * DD + c0) = make_float2(v0, v1);
                }
            }
        }
    }
}

// ---------------- global mean pool (fp16 in -> fp16 out) ----------------
__global__ void k_pool() {
    int g = blockIdx.x;
    int t = threadIdx.x;
    int s = g_goff[g], e = g_goff[g + 1];
    float a0 = 0.f, a1 = 0.f, a2 = 0.f, a3 = 0.f;
    int i = s;
    for (; i + 3 < e; i += 4) {
        a0 += __half2float(g_hx[(size_t)(i + 0) * DD + t]);
        a1 += __half2float(g_hx[(size_t)(i + 1) * DD + t]);
        a2 += __half2float(g_hx[(size_t)(i + 2) * DD + t]);
        a3 += __half2float(g_hx[(size_t)(i + 3) * DD + t]);
    }
    for (; i < e; i++) a0 += __half2float(g_hx[(size_t)i * DD + t]);
    float cnt = (float)((e - s) > 0 ? (e - s) : 1);
    g_pf[g * DD + t] = __float2half_rn((a0 + a1 + a2 + a3) / cnt);
}

// ---------------- launch ----------------
extern "C" void kernel_launch(void* const* d_in, const int* in_sizes, int n_in,
                              void* d_out, int out_size) {
    const float* x     = (const float*)d_in[0];
    const int*   ei    = (const int*)d_in[1];
    const int*   batch = (const int*)d_in[2];
    const float* W1    = (const float*)d_in[3];
    const float* b1    = (const float*)d_in[4];
    const float* W2    = (const float*)d_in[5];
    const float* b2    = (const float*)d_in[6];
    const float* gamma = (const float*)d_in[7];
    const float* beta  = (const float*)d_in[8];
    const float* rmean = (const float*)d_in[9];
    const float* rvar  = (const float*)d_in[10];
    const float* eps   = (const float*)d_in[11];
    const float* linW  = (const float*)d_in[12];
    const float* linb  = (const float*)d_in[13];
    float* out = (float*)d_out;

    const int* src = ei;
    const int* dst = ei + EE;

    __half *paf, *pwh, *pwl;
    void *pdeg, *pgcnt;
    cudaGetSymbolAddress((void**)&paf, g_af);
    cudaGetSymbolAddress((void**)&pwh, g_wh);
    cudaGetSymbolAddress((void**)&pwl, g_wl);
    cudaGetSymbolAddress(&pdeg, g_deg);
    cudaGetSymbolAddress(&pgcnt, g_gcnt);

    cudaFuncSetAttribute(k_layer, cudaFuncAttributeMaxDynamicSharedMemorySize, SMEM_F);
    cudaFuncSetAttribute(k_lin,   cudaFuncAttributeMaxDynamicSharedMemorySize, SMEM_L);

    k_wconv<<<(7 * DD * DD + 255) / 256, 256>>>(W1, W2, linW);
    k_xconv<<<(NN * DD / 4 + 255) / 256, 256>>>(x);

    // CSR + pool offsets
    cudaMemsetAsync(pdeg, 0, NN * sizeof(int));
    cudaMemsetAsync(pgcnt, 0, GG * sizeof(int));
    k_counts<<<(EE / 4 + 255) / 256, 256>>>(dst, batch);
    int nb = (NN + SCAN_B - 1) / SCAN_B;
    k_scan1<<<nb, SCAN_B>>>();
    k_scan2<<<1, 256>>>(nb);
    k_scan3<<<nb, SCAN_B>>>();
    k_fill<<<(EE / 4 + 255) / 256, 256>>>(src, dst);
    k_scan_g<<<1, GG>>>();

    for (int l = 0; l < LL; l++) {
        k_agg<<<NN / 8, 256>>>(eps, l);
        k_layer<<<NSM, 256, SMEM_F>>>(paf,
                pwh + l * DD * DD,       pwl + l * DD * DD,
                pwh + (3 + l) * DD * DD, pwl + (3 + l) * DD * DD,
                b1 + l * DD, b2 + l * DD,
                gamma + l * DD, beta + l * DD, rmean + l * DD, rvar + l * DD, NN);
    }

    k_pool<<<GG, DD>>>();
    k_lin<<<(GG + 127) / 128, 256, SMEM_L>>>(pwh + 6 * DD * DD, pwl + 6 * DD * DD,
                                             linb, out, GG);
}